// round 1
// baseline (speedup 1.0000x reference)
#include <cuda_runtime.h>
#include <cuda_bf16.h>
#include <cstddef>

#define DIM    1024
#define INNER  1024
#define NHEAD  16
#define DHEAD  64
#define BATCH  2
#define SEQ    2048
#define MROWS  (BATCH * SEQ)
#define ATTN_SCALE 0.125f   // 64^-0.5

#define PADW 65   // 64 + 1 padding to break smem bank conflicts

// Scratch (allocation-free rule: __device__ globals)
__device__ float g_q[MROWS * INNER];
__device__ float g_k[MROWS * INNER];
__device__ float g_v[MROWS * INNER];
__device__ float g_a[MROWS * INNER];

// ---------------------------------------------------------------------------
// GEMM: C[M,N] = A[M,K] @ B[K,N] (+ optional bias[N])
// 128x128 block tile, BK=8, 256 threads, 8x8 microtile per thread.
// M % 128 == 0, N % 128 == 0, K % 8 == 0 guaranteed by problem shapes.
// ---------------------------------------------------------------------------
__global__ __launch_bounds__(256, 2)
void gemm128(const float* __restrict__ A, const float* __restrict__ B,
             const float* __restrict__ bias, float* __restrict__ C,
             int M, int N, int K) {
    __shared__ float As[8][128];
    __shared__ float Bs[8][128];

    const int tid = threadIdx.x;
    const int bx = blockIdx.x, by = blockIdx.y;
    const int tx = tid & 15, ty = tid >> 4;
    const int row0 = by * 128 + ty * 8;
    const int col0 = bx * 128 + tx * 8;

    // A tile loader: 128 rows x 8 cols; each thread one float4
    const int arow = tid >> 1;
    const int acol = (tid & 1) * 4;
    // B tile loader: 8 rows x 128 cols; each thread one float4
    const int brow = tid >> 5;
    const int bcol = (tid & 31) * 4;

    const float* Aptr = A + (size_t)(by * 128 + arow) * K + acol;
    const float* Bptr = B + (size_t)brow * N + bx * 128 + bcol;

    float acc[8][8];
#pragma unroll
    for (int i = 0; i < 8; i++)
#pragma unroll
        for (int j = 0; j < 8; j++) acc[i][j] = 0.f;

    for (int k0 = 0; k0 < K; k0 += 8) {
        float4 av = *(const float4*)(Aptr + k0);
        As[acol + 0][arow] = av.x;
        As[acol + 1][arow] = av.y;
        As[acol + 2][arow] = av.z;
        As[acol + 3][arow] = av.w;
        *(float4*)&Bs[brow][bcol] = *(const float4*)(Bptr + (size_t)k0 * N);
        __syncthreads();

#pragma unroll
        for (int kk = 0; kk < 8; kk++) {
            float a[8], b[8];
#pragma unroll
            for (int i = 0; i < 8; i++) a[i] = As[kk][ty * 8 + i];
#pragma unroll
            for (int j = 0; j < 8; j++) b[j] = Bs[kk][tx * 8 + j];
#pragma unroll
            for (int i = 0; i < 8; i++)
#pragma unroll
                for (int j = 0; j < 8; j++)
                    acc[i][j] = fmaf(a[i], b[j], acc[i][j]);
        }
        __syncthreads();
    }

#pragma unroll
    for (int i = 0; i < 8; i++) {
#pragma unroll
        for (int j = 0; j < 8; j += 4) {
            float4 v;
            v.x = acc[i][j + 0];
            v.y = acc[i][j + 1];
            v.z = acc[i][j + 2];
            v.w = acc[i][j + 3];
            if (bias != nullptr) {
                v.x += bias[col0 + j + 0];
                v.y += bias[col0 + j + 1];
                v.z += bias[col0 + j + 2];
                v.w += bias[col0 + j + 3];
            }
            *(float4*)&C[(size_t)(row0 + i) * N + col0 + j] = v;
        }
    }
}

// ---------------------------------------------------------------------------
// Flash-style attention. One block = one (b, h, 64-query tile).
// 256 threads, 4x4 microtiles (16x16 thread grid), online softmax.
// Q/K/V laid out [B, S, H*Dh] (head offset h*64, row stride INNER).
// ---------------------------------------------------------------------------
__global__ __launch_bounds__(256, 2)
void attn_kernel(const float* __restrict__ Q, const float* __restrict__ K,
                 const float* __restrict__ V, float* __restrict__ O) {
    extern __shared__ float sm[];
    float* Qs = sm;                  // [64][PADW]
    float* Ks = sm + 64 * PADW;      // [64][PADW]
    float* Vs = sm + 2 * 64 * PADW;  // [64][PADW]
    float* Ps = sm + 3 * 64 * PADW;  // [64][PADW]

    const int tid = threadIdx.x;
    const int tx = tid & 15, ty = tid >> 4;
    const int qt = blockIdx.x;   // query tile
    const int h  = blockIdx.y;
    const int b  = blockIdx.z;

    const float* Qb = Q + ((size_t)(b * SEQ + qt * 64)) * INNER + h * DHEAD;
    const float* Kb = K + (size_t)b * SEQ * INNER + h * DHEAD;
    const float* Vb = V + (size_t)b * SEQ * INNER + h * DHEAD;

    // Load Q tile (pre-scaled). Each thread: 16 floats of one row.
    const int lr = tid >> 2;            // 0..63
    const int lc = (tid & 3) * 16;      // 0,16,32,48
    {
#pragma unroll
        for (int j = 0; j < 16; j += 4) {
            float4 v = *(const float4*)&Qb[(size_t)lr * INNER + lc + j];
            Qs[lr * PADW + lc + j + 0] = v.x * ATTN_SCALE;
            Qs[lr * PADW + lc + j + 1] = v.y * ATTN_SCALE;
            Qs[lr * PADW + lc + j + 2] = v.z * ATTN_SCALE;
            Qs[lr * PADW + lc + j + 3] = v.w * ATTN_SCALE;
        }
    }

    float m_i[4], l_i[4], o[4][4];
#pragma unroll
    for (int i = 0; i < 4; i++) {
        m_i[i] = -1e30f;
        l_i[i] = 0.f;
#pragma unroll
        for (int j = 0; j < 4; j++) o[i][j] = 0.f;
    }

    for (int kt = 0; kt < SEQ / 64; kt++) {
        __syncthreads();  // previous iter's Ks/Vs/Ps reads done (also covers Qs on iter 0)
#pragma unroll
        for (int j = 0; j < 16; j += 4) {
            float4 kv = *(const float4*)&Kb[((size_t)(kt * 64 + lr)) * INNER + lc + j];
            Ks[lr * PADW + lc + j + 0] = kv.x;
            Ks[lr * PADW + lc + j + 1] = kv.y;
            Ks[lr * PADW + lc + j + 2] = kv.z;
            Ks[lr * PADW + lc + j + 3] = kv.w;
            float4 vv = *(const float4*)&Vb[((size_t)(kt * 64 + lr)) * INNER + lc + j];
            Vs[lr * PADW + lc + j + 0] = vv.x;
            Vs[lr * PADW + lc + j + 1] = vv.y;
            Vs[lr * PADW + lc + j + 2] = vv.z;
            Vs[lr * PADW + lc + j + 3] = vv.w;
        }
        __syncthreads();

        // Scores: s[i][j] = sum_k Qs[ty*4+i][k] * Ks[tx*4+j][k]
        float s[4][4];
#pragma unroll
        for (int i = 0; i < 4; i++)
#pragma unroll
            for (int j = 0; j < 4; j++) s[i][j] = 0.f;

#pragma unroll 16
        for (int kk = 0; kk < 64; kk++) {
            float a[4], bb[4];
#pragma unroll
            for (int i = 0; i < 4; i++) a[i] = Qs[(ty * 4 + i) * PADW + kk];
#pragma unroll
            for (int j = 0; j < 4; j++) bb[j] = Ks[(tx * 4 + j) * PADW + kk];
#pragma unroll
            for (int i = 0; i < 4; i++)
#pragma unroll
                for (int j = 0; j < 4; j++)
                    s[i][j] = fmaf(a[i], bb[j], s[i][j]);
        }

        // Online softmax update per row (rows owned by the 16 tx-lanes of a ty group)
#pragma unroll
        for (int i = 0; i < 4; i++) {
            float mx = fmaxf(fmaxf(s[i][0], s[i][1]), fmaxf(s[i][2], s[i][3]));
#pragma unroll
            for (int off = 8; off > 0; off >>= 1)
                mx = fmaxf(mx, __shfl_xor_sync(0xffffffffu, mx, off, 16));
            float mnew = fmaxf(m_i[i], mx);
            float alpha = __expf(m_i[i] - mnew);
            float sum = 0.f;
#pragma unroll
            for (int j = 0; j < 4; j++) {
                float p = __expf(s[i][j] - mnew);
                s[i][j] = p;
                sum += p;
            }
#pragma unroll
            for (int off = 8; off > 0; off >>= 1)
                sum += __shfl_xor_sync(0xffffffffu, sum, off, 16);
            l_i[i] = l_i[i] * alpha + sum;
            m_i[i] = mnew;
#pragma unroll
            for (int j = 0; j < 4; j++) o[i][j] *= alpha;
#pragma unroll
            for (int j = 0; j < 4; j++)
                Ps[(ty * 4 + i) * PADW + tx * 4 + j] = s[i][j];
        }
        __syncthreads();

        // PV: o[i][j] += sum_key Ps[ty*4+i][key] * Vs[key][tx*4+j]
#pragma unroll 16
        for (int key = 0; key < 64; key++) {
            float a[4], vv[4];
#pragma unroll
            for (int i = 0; i < 4; i++) a[i] = Ps[(ty * 4 + i) * PADW + key];
#pragma unroll
            for (int j = 0; j < 4; j++) vv[j] = Vs[key * PADW + tx * 4 + j];
#pragma unroll
            for (int i = 0; i < 4; i++)
#pragma unroll
                for (int j = 0; j < 4; j++)
                    o[i][j] = fmaf(a[i], vv[j], o[i][j]);
        }
    }

    // Epilogue: normalize and write [B,S,H*Dh]
    float* Ob = O + ((size_t)(b * SEQ + qt * 64)) * INNER + h * DHEAD;
#pragma unroll
    for (int i = 0; i < 4; i++) {
        float inv = 1.f / l_i[i];
#pragma unroll
        for (int j = 0; j < 4; j++)
            Ob[(size_t)(ty * 4 + i) * INNER + tx * 4 + j] = o[i][j] * inv;
    }
}

// ---------------------------------------------------------------------------
extern "C" void kernel_launch(void* const* d_in, const int* in_sizes, int n_in,
                              void* d_out, int out_size) {
    const float* x  = (const float*)d_in[0];
    const float* Wq = (const float*)d_in[1];
    const float* Wk = (const float*)d_in[2];
    const float* Wv = (const float*)d_in[3];
    const float* Wo = (const float*)d_in[4];
    const float* bo = (const float*)d_in[5];
    float* out = (float*)d_out;

    float *q, *k, *v, *a;
    cudaGetSymbolAddress((void**)&q, g_q);
    cudaGetSymbolAddress((void**)&k, g_k);
    cudaGetSymbolAddress((void**)&v, g_v);
    cudaGetSymbolAddress((void**)&a, g_a);

    const int attn_smem = 4 * 64 * PADW * (int)sizeof(float);
    cudaFuncSetAttribute(attn_kernel, cudaFuncAttributeMaxDynamicSharedMemorySize,
                         attn_smem);

    dim3 gproj(INNER / 128, MROWS / 128);   // (8, 32)
    gemm128<<<gproj, 256>>>(x, Wq, nullptr, q, MROWS, INNER, DIM);
    gemm128<<<gproj, 256>>>(x, Wk, nullptr, k, MROWS, INNER, DIM);
    gemm128<<<gproj, 256>>>(x, Wv, nullptr, v, MROWS, INNER, DIM);

    attn_kernel<<<dim3(SEQ / 64, NHEAD, BATCH), 256, attn_smem>>>(q, k, v, a);

    gemm128<<<dim3(DIM / 128, MROWS / 128), 256>>>(a, Wo, bo, out, MROWS, DIM, INNER);
}

// round 3
// speedup vs baseline: 1.3295x; 1.3295x over previous
#include <cuda_runtime.h>
#include <cuda_bf16.h>
#include <mma.h>
#include <cstddef>

using namespace nvcuda;

#define DIM    1024
#define INNER  1024
#define NHEAD  16
#define DHEAD  64
#define BATCH  2
#define SEQ    2048
#define MROWS  (BATCH * SEQ)
#define ATTN_SCALE 0.125f   // 64^-0.5

// Scratch (allocation-free rule: __device__ globals)
__device__ float g_q[MROWS * INNER];
__device__ float g_k[MROWS * INNER];
__device__ float g_v[MROWS * INNER];
__device__ float g_a[MROWS * INNER];

__device__ __forceinline__ float to_tf32(float x) {
    unsigned r;
    asm("cvt.rna.tf32.f32 %0, %1;" : "=r"(r) : "f"(x));
    return __uint_as_float(r);
}

typedef wmma::fragment<wmma::matrix_a, 16, 16, 8, wmma::precision::tf32, wmma::row_major> FragA;
typedef wmma::fragment<wmma::matrix_a, 16, 16, 8, wmma::precision::tf32, wmma::col_major> FragAc;
typedef wmma::fragment<wmma::matrix_b, 16, 16, 8, wmma::precision::tf32, wmma::row_major> FragB;
typedef wmma::fragment<wmma::matrix_b, 16, 16, 8, wmma::precision::tf32, wmma::col_major> FragBc;
typedef wmma::fragment<wmma::accumulator, 16, 16, 8, float> FragC;

// ---------------------------------------------------------------------------
// tf32 GEMM: C[M,N] = A[M,K] @ B[K,N]. Block 128x128, BK=32, 256 threads.
// Warp grid 4(M) x 2(N): warp tile 32x64, 2x4 acc fragments.
// M%128==0, N%128==0, K%32==0.
// ---------------------------------------------------------------------------
__global__ __launch_bounds__(256)
void gemm_tf32(const float* __restrict__ A, const float* __restrict__ B,
               float* __restrict__ C, int M, int N, int K) {
    __shared__ float As[128 * 40];   // [128 rows][32 k + pad8]
    __shared__ float Bs[32 * 136];   // [32 k][128 n + pad8]

    const int tid = threadIdx.x;
    const int warp = tid >> 5;
    const int wm = warp >> 1;        // 0..3
    const int wn = warp & 1;         // 0..1
    const int bx = blockIdx.x, by = blockIdx.y;

    FragC acc[2][4];
#pragma unroll
    for (int mi = 0; mi < 2; mi++)
#pragma unroll
        for (int nf = 0; nf < 4; nf++) wmma::fill_fragment(acc[mi][nf], 0.f);

    const int arow = tid >> 3;          // 0..31 (4 passes of 32 rows)
    const int akc  = (tid & 7) * 4;     // 0..28
    const int brow = tid >> 5;          // 0..7 (4 passes of 8 rows)
    const int bcol = (tid & 31) * 4;    // 0..124

    const float* Ag = A + (size_t)(by * 128) * K;
    const float* Bg = B + bx * 128;

    for (int k0 = 0; k0 < K; k0 += 32) {
        __syncthreads();
#pragma unroll
        for (int p = 0; p < 4; p++) {
            int r = p * 32 + arow;
            float4 v = *(const float4*)(Ag + (size_t)r * K + k0 + akc);
            float* d = As + r * 40 + akc;
            d[0] = to_tf32(v.x); d[1] = to_tf32(v.y);
            d[2] = to_tf32(v.z); d[3] = to_tf32(v.w);
        }
#pragma unroll
        for (int p = 0; p < 4; p++) {
            int r = p * 8 + brow;
            float4 v = *(const float4*)(Bg + (size_t)(k0 + r) * N + bcol);
            float* d = Bs + r * 136 + bcol;
            d[0] = to_tf32(v.x); d[1] = to_tf32(v.y);
            d[2] = to_tf32(v.z); d[3] = to_tf32(v.w);
        }
        __syncthreads();

#pragma unroll
        for (int kf = 0; kf < 4; kf++) {
            FragA a0, a1;
            wmma::load_matrix_sync(a0, As + (wm * 32) * 40 + kf * 8, 40);
            wmma::load_matrix_sync(a1, As + (wm * 32 + 16) * 40 + kf * 8, 40);
#pragma unroll
            for (int nf = 0; nf < 4; nf++) {
                FragB b;
                wmma::load_matrix_sync(b, Bs + (kf * 8) * 136 + wn * 64 + nf * 16, 136);
                wmma::mma_sync(acc[0][nf], a0, b, acc[0][nf]);
                wmma::mma_sync(acc[1][nf], a1, b, acc[1][nf]);
            }
        }
    }

#pragma unroll
    for (int mi = 0; mi < 2; mi++)
#pragma unroll
        for (int nf = 0; nf < 4; nf++)
            wmma::store_matrix_sync(
                C + (size_t)(by * 128 + wm * 32 + mi * 16) * N + bx * 128 + wn * 64 + nf * 16,
                acc[mi][nf], N, wmma::mem_row_major);
}

// ---------------------------------------------------------------------------
// Bias add for the final output: out[r*DIM + c] += bo[c]
// ---------------------------------------------------------------------------
__global__ void bias_add(float* __restrict__ out, const float* __restrict__ bo) {
    int i = blockIdx.x * blockDim.x + threadIdx.x;   // float4 index
    int c = (i & (DIM / 4 - 1)) * 4;
    float4 v = ((float4*)out)[i];
    v.x += bo[c + 0]; v.y += bo[c + 1]; v.z += bo[c + 2]; v.w += bo[c + 3];
    ((float4*)out)[i] = v;
}

// ---------------------------------------------------------------------------
// Flash attention with tf32 wmma. One block = (b, h, 128-query tile).
// 256 threads = 8 warps; warp w owns query rows [16w, 16w+16).
// S tile stored col-major (key-major) in smem -> conflict-free row softmax.
// KV tile = 128 keys, 16 tiles over SEQ=2048.
// ---------------------------------------------------------------------------
#define QT  128
#define KT  128
#define LDQ 72    // ld for Qs/Ks/Vs/Osc [row][64 + pad8]
#define LDP 136   // ld for Ps [key][128 qrows + pad8]

__global__ __launch_bounds__(256, 1)
void attn_tf32(const float* __restrict__ Q, const float* __restrict__ K,
               const float* __restrict__ V, float* __restrict__ O) {
    extern __shared__ float sm[];
    float* Qs      = sm;                      // [128][72]  tf32 Q (pre-scaled)
    float* Vs      = Qs + QT * LDQ;           // [128][72]  tf32 V (key-major)
    float* KOs     = Vs + KT * LDQ;           // union: Ks [128][72] / Osc [128][72]
    float* Ps      = KOs + KT * LDQ;          // [128 key][136] scores / tf32 P
    float* alpha_s = Ps + KT * LDP;           // [128]
    float* linv_s  = alpha_s + QT;            // [128]

    const int tid  = threadIdx.x;
    const int warp = tid >> 5;
    const int qt = blockIdx.x, h = blockIdx.y, b = blockIdx.z;

    const float* Qb = Q + ((size_t)(b * SEQ + qt * QT)) * INNER + h * DHEAD;
    const float* Kb = K + (size_t)b * SEQ * INNER + h * DHEAD;
    const float* Vb = V + (size_t)b * SEQ * INNER + h * DHEAD;

    const int lr = tid >> 1;           // 0..127 (row)
    const int lc = (tid & 1) * 32;     // 0 or 32

    // Load Q tile, scale, convert to tf32.
#pragma unroll
    for (int j = 0; j < 32; j += 4) {
        float4 v = *(const float4*)&Qb[(size_t)lr * INNER + lc + j];
        float* d = Qs + lr * LDQ + lc + j;
        d[0] = to_tf32(v.x * ATTN_SCALE); d[1] = to_tf32(v.y * ATTN_SCALE);
        d[2] = to_tf32(v.z * ATTN_SCALE); d[3] = to_tf32(v.w * ATTN_SCALE);
    }

    float m_i = -1e30f, l_i = 0.f;     // valid for tid < 128 (row tid)
    float o_reg[32];
#pragma unroll
    for (int j = 0; j < 32; j++) o_reg[j] = 0.f;

    for (int kt = 0; kt < SEQ / KT; kt++) {
        __syncthreads();   // prior-iter readers of KOs/Vs done (and Q store on iter 0)

        // Load K, V tiles (tf32, key-major rows)
#pragma unroll
        for (int j = 0; j < 32; j += 4) {
            float4 kv = *(const float4*)&Kb[((size_t)(kt * KT + lr)) * INNER + lc + j];
            float* dk = KOs + lr * LDQ + lc + j;
            dk[0] = to_tf32(kv.x); dk[1] = to_tf32(kv.y);
            dk[2] = to_tf32(kv.z); dk[3] = to_tf32(kv.w);
            float4 vv = *(const float4*)&Vb[((size_t)(kt * KT + lr)) * INNER + lc + j];
            float* dv = Vs + lr * LDQ + lc + j;
            dv[0] = to_tf32(vv.x); dv[1] = to_tf32(vv.y);
            dv[2] = to_tf32(vv.z); dv[3] = to_tf32(vv.w);
        }
        __syncthreads();

        // ---- S = Q @ K^T : warp computes rows [16w,16w+16) x all 128 keys ----
        {
            FragA af[8];
#pragma unroll
            for (int kf = 0; kf < 8; kf++)
                wmma::load_matrix_sync(af[kf], Qs + (warp * 16) * LDQ + kf * 8, LDQ);
#pragma unroll
            for (int nf = 0; nf < 8; nf++) {
                FragC acc;
                wmma::fill_fragment(acc, 0.f);
#pragma unroll
                for (int kf = 0; kf < 8; kf++) {
                    FragBc bf;
                    wmma::load_matrix_sync(bf, KOs + (nf * 16) * LDQ + kf * 8, LDQ);
                    wmma::mma_sync(acc, af[kf], bf, acc);
                }
                // store col-major: element (m=qrow, n=key) -> Ps[key*LDP + qrow]
                wmma::store_matrix_sync(Ps + (nf * 16) * LDP + warp * 16, acc, LDP,
                                        wmma::mem_col_major);
            }
        }
        __syncthreads();

        // ---- online softmax: thread r < 128 owns query row r ----
        if (tid < 128) {
            const int r = tid;
            float mx = -1e30f;
#pragma unroll 8
            for (int k = 0; k < KT; k++)
                mx = fmaxf(mx, Ps[k * LDP + r]);
            float mnew = fmaxf(m_i, mx);
            float alpha = __expf(m_i - mnew);
            float sum = 0.f;
#pragma unroll 8
            for (int k = 0; k < KT; k++) {
                float p = __expf(Ps[k * LDP + r] - mnew);
                Ps[k * LDP + r] = to_tf32(p);
                sum += p;
            }
            l_i = l_i * alpha + sum;
            m_i = mnew;
            alpha_s[r] = alpha;
        }
        __syncthreads();

        // ---- PV: [16 qrows x 64 dims] += P[16 x 128keys] @ V[128keys x 64] ----
        {
            FragC acc2[4];
#pragma unroll
            for (int nf = 0; nf < 4; nf++) wmma::fill_fragment(acc2[nf], 0.f);
#pragma unroll
            for (int kf = 0; kf < 16; kf++) {
                FragAc af;   // P col-major: (m,k) at Ps[k*LDP + m]
                wmma::load_matrix_sync(af, Ps + (kf * 8) * LDP + warp * 16, LDP);
#pragma unroll
                for (int nf = 0; nf < 4; nf++) {
                    FragB bf;
                    wmma::load_matrix_sync(bf, Vs + (kf * 8) * LDQ + nf * 16, LDQ);
                    wmma::mma_sync(acc2[nf], af, bf, acc2[nf]);
                }
            }
#pragma unroll
            for (int nf = 0; nf < 4; nf++)
                wmma::store_matrix_sync(KOs + (warp * 16) * LDQ + nf * 16, acc2[nf],
                                        LDQ, wmma::mem_row_major);   // Osc
        }
        __syncthreads();

        // ---- O rescale + accumulate (registers), 2 threads per row ----
        {
            float a = alpha_s[lr];
#pragma unroll
            for (int j = 0; j < 32; j += 4) {
                float4 v = *(const float4*)(KOs + lr * LDQ + lc + j);
                o_reg[j + 0] = o_reg[j + 0] * a + v.x;
                o_reg[j + 1] = o_reg[j + 1] * a + v.y;
                o_reg[j + 2] = o_reg[j + 2] * a + v.z;
                o_reg[j + 3] = o_reg[j + 3] * a + v.w;
            }
        }
    }

    if (tid < 128) linv_s[tid] = 1.f / l_i;
    __syncthreads();

    // write out [B,S,H*Dh]
    float* Ob = O + ((size_t)(b * SEQ + qt * QT + lr)) * INNER + h * DHEAD + lc;
    float inv = linv_s[lr];
#pragma unroll
    for (int j = 0; j < 32; j += 4) {
        float4 v;
        v.x = o_reg[j + 0] * inv; v.y = o_reg[j + 1] * inv;
        v.z = o_reg[j + 2] * inv; v.w = o_reg[j + 3] * inv;
        *(float4*)(Ob + j) = v;
    }
}

// ---------------------------------------------------------------------------
extern "C" void kernel_launch(void* const* d_in, const int* in_sizes, int n_in,
                              void* d_out, int out_size) {
    const float* x  = (const float*)d_in[0];
    const float* Wq = (const float*)d_in[1];
    const float* Wk = (const float*)d_in[2];
    const float* Wv = (const float*)d_in[3];
    const float* Wo = (const float*)d_in[4];
    const float* bo = (const float*)d_in[5];
    float* out = (float*)d_out;

    float *q, *k, *v, *a;
    cudaGetSymbolAddress((void**)&q, g_q);
    cudaGetSymbolAddress((void**)&k, g_k);
    cudaGetSymbolAddress((void**)&v, g_v);
    cudaGetSymbolAddress((void**)&a, g_a);

    const int attn_smem = (3 * QT * LDQ + KT * LDP + 2 * QT) * (int)sizeof(float);
    cudaFuncSetAttribute(attn_tf32, cudaFuncAttributeMaxDynamicSharedMemorySize,
                         attn_smem);

    dim3 gproj(INNER / 128, MROWS / 128);   // (8, 32)
    gemm_tf32<<<gproj, 256>>>(x, Wq, q, MROWS, INNER, DIM);
    gemm_tf32<<<gproj, 256>>>(x, Wk, k, MROWS, INNER, DIM);
    gemm_tf32<<<gproj, 256>>>(x, Wv, v, MROWS, INNER, DIM);

    attn_tf32<<<dim3(SEQ / QT, NHEAD, BATCH), 256, attn_smem>>>(q, k, v, a);

    gemm_tf32<<<dim3(DIM / 128, MROWS / 128), 256>>>(a, Wo, out, MROWS, DIM, INNER);
    bias_add<<<(MROWS * DIM / 4) / 256, 256>>>(out, bo);
}

// round 4
// speedup vs baseline: 1.7832x; 1.3413x over previous
#include <cuda_runtime.h>
#include <cuda_bf16.h>
#include <mma.h>
#include <cstddef>

using namespace nvcuda;

#define DIM    1024
#define INNER  1024
#define NHEAD  16
#define DHEAD  64
#define BATCH  2
#define SEQ    2048
#define MROWS  (BATCH * SEQ)
#define ATTN_SCALE 0.125f   // 64^-0.5

// Scratch (allocation-free rule: __device__ globals)
__device__ float g_q[MROWS * INNER];
__device__ float g_k[MROWS * INNER];
__device__ float g_v[MROWS * INNER];
__device__ float g_a[MROWS * INNER];

__device__ __forceinline__ float to_tf32(float x) {
    unsigned r;
    asm("cvt.rna.tf32.f32 %0, %1;" : "=r"(r) : "f"(x));
    return __uint_as_float(r);
}
__device__ __forceinline__ unsigned tf32u(float x) {
    unsigned r;
    asm("cvt.rna.tf32.f32 %0, %1;" : "=r"(r) : "f"(x));
    return r;
}

// mma.m16n8k8 tf32: D += A*B, C/D in fp32 regs, A 4 regs, B 2 regs.
__device__ __forceinline__ void mma_tf32(float c[4], const unsigned a[4],
                                         unsigned b0, unsigned b1) {
    asm volatile(
        "mma.sync.aligned.m16n8k8.row.col.f32.tf32.tf32.f32 "
        "{%0,%1,%2,%3}, {%4,%5,%6,%7}, {%8,%9}, {%0,%1,%2,%3};\n"
        : "+f"(c[0]), "+f"(c[1]), "+f"(c[2]), "+f"(c[3])
        : "r"(a[0]), "r"(a[1]), "r"(a[2]), "r"(a[3]), "r"(b0), "r"(b1));
}

typedef wmma::fragment<wmma::matrix_a, 16, 16, 8, wmma::precision::tf32, wmma::row_major> FragA;
typedef wmma::fragment<wmma::matrix_b, 16, 16, 8, wmma::precision::tf32, wmma::row_major> FragB;
typedef wmma::fragment<wmma::accumulator, 16, 16, 8, float> FragC;

// ---------------------------------------------------------------------------
// tf32 GEMM: C[M,N] = A[M,K] @ B[K,N]. Block 128x128, BK=32, 256 threads.
// Register prefetch of next K-slab overlaps LDG with the mma section.
// ---------------------------------------------------------------------------
__global__ __launch_bounds__(256)
void gemm_tf32(const float* __restrict__ A, const float* __restrict__ B,
               float* __restrict__ C, int M, int N, int K) {
    __shared__ float As[128 * 40];
    __shared__ float Bs[32 * 136];

    const int tid = threadIdx.x;
    const int warp = tid >> 5;
    const int wm = warp >> 1;
    const int wn = warp & 1;
    const int bx = blockIdx.x, by = blockIdx.y;

    FragC acc[2][4];
#pragma unroll
    for (int mi = 0; mi < 2; mi++)
#pragma unroll
        for (int nf = 0; nf < 4; nf++) wmma::fill_fragment(acc[mi][nf], 0.f);

    const int arow = tid >> 3;
    const int akc  = (tid & 7) * 4;
    const int brow = tid >> 5;
    const int bcol = (tid & 31) * 4;

    const float* Ag = A + (size_t)(by * 128) * K;
    const float* Bg = B + bx * 128;

    float4 aReg[4], bReg[4];
#pragma unroll
    for (int p = 0; p < 4; p++)
        aReg[p] = *(const float4*)(Ag + (size_t)(p * 32 + arow) * K + akc);
#pragma unroll
    for (int p = 0; p < 4; p++)
        bReg[p] = *(const float4*)(Bg + (size_t)(p * 8 + brow) * N + bcol);

    for (int k0 = 0; k0 < K; k0 += 32) {
#pragma unroll
        for (int p = 0; p < 4; p++) {
            float* d = As + (p * 32 + arow) * 40 + akc;
            d[0] = to_tf32(aReg[p].x); d[1] = to_tf32(aReg[p].y);
            d[2] = to_tf32(aReg[p].z); d[3] = to_tf32(aReg[p].w);
        }
#pragma unroll
        for (int p = 0; p < 4; p++) {
            float* d = Bs + (p * 8 + brow) * 136 + bcol;
            d[0] = to_tf32(bReg[p].x); d[1] = to_tf32(bReg[p].y);
            d[2] = to_tf32(bReg[p].z); d[3] = to_tf32(bReg[p].w);
        }
        __syncthreads();

        if (k0 + 32 < K) {
#pragma unroll
            for (int p = 0; p < 4; p++)
                aReg[p] = *(const float4*)(Ag + (size_t)(p * 32 + arow) * K + k0 + 32 + akc);
#pragma unroll
            for (int p = 0; p < 4; p++)
                bReg[p] = *(const float4*)(Bg + (size_t)(k0 + 32 + p * 8 + brow) * N + bcol);
        }

#pragma unroll
        for (int kf = 0; kf < 4; kf++) {
            FragA a0, a1;
            wmma::load_matrix_sync(a0, As + (wm * 32) * 40 + kf * 8, 40);
            wmma::load_matrix_sync(a1, As + (wm * 32 + 16) * 40 + kf * 8, 40);
#pragma unroll
            for (int nf = 0; nf < 4; nf++) {
                FragB b;
                wmma::load_matrix_sync(b, Bs + (kf * 8) * 136 + wn * 64 + nf * 16, 136);
                wmma::mma_sync(acc[0][nf], a0, b, acc[0][nf]);
                wmma::mma_sync(acc[1][nf], a1, b, acc[1][nf]);
            }
        }
        __syncthreads();
    }

#pragma unroll
    for (int mi = 0; mi < 2; mi++)
#pragma unroll
        for (int nf = 0; nf < 4; nf++)
            wmma::store_matrix_sync(
                C + (size_t)(by * 128 + wm * 32 + mi * 16) * N + bx * 128 + wn * 64 + nf * 16,
                acc[mi][nf], N, wmma::mem_row_major);
}

__global__ void bias_add(float* __restrict__ out, const float* __restrict__ bo) {
    int i = blockIdx.x * blockDim.x + threadIdx.x;
    int c = (i & (DIM / 4 - 1)) * 4;
    float4 v = ((float4*)out)[i];
    v.x += bo[c + 0]; v.y += bo[c + 1]; v.z += bo[c + 2]; v.w += bo[c + 3];
    ((float4*)out)[i] = v;
}

// ---------------------------------------------------------------------------
// FlashAttention-2 style, register-resident, raw mma.m16n8k8 tf32.
// CTA = (b, h, 128-q tile); 8 warps, warp owns 16 q rows. KV tile = 128 keys.
// K smem swizzle: col' = col ^ ((row&7)<<2)  -> conflict-free QK B-frag loads
// V smem swizzle: col' = col ^ ((row&7)<<3)  -> conflict-free PV B-frag loads
// P: warp-private [16][132] row-major       -> conflict-free A-frag loads
// ---------------------------------------------------------------------------
#define QT 128
#define KT 128
#define LDPW 132

__global__ __launch_bounds__(256, 1)
void attn_fa2(const float* __restrict__ Q, const float* __restrict__ K,
              const float* __restrict__ V, float* __restrict__ O) {
    extern __shared__ float sm[];
    float* Ks = sm;                 // [128][64] swizzled <<2
    float* Vs = sm + 128 * 64;      // [128][64] swizzled <<3
    float* Ps = sm + 2 * 128 * 64;  // 8 warps x [16][132]

    const int tid  = threadIdx.x;
    const int warp = tid >> 5;
    const int lane = tid & 31;
    const int g = lane >> 2;        // groupID 0..7
    const int t = lane & 3;         // threadID in group
    const int qt = blockIdx.x, h = blockIdx.y, b = blockIdx.z;

    const float* Qb = Q + ((size_t)(b * SEQ + qt * QT)) * INNER + h * DHEAD;
    const float* Kb = K + (size_t)b * SEQ * INNER + h * DHEAD;
    const float* Vb = V + (size_t)b * SEQ * INNER + h * DHEAD;
    float* Pw = Ps + warp * 16 * LDPW;

    const int lr = tid >> 1;        // 0..127
    const int lc = (tid & 1) * 32;  // 0 / 32

    // ---- stage Q tile (plain layout, pre-scaled) then pull A fragments ----
#pragma unroll
    for (int j = 0; j < 32; j += 4) {
        float4 v = *(const float4*)&Qb[(size_t)lr * INNER + lc + j];
        float* d = Ks + lr * 64 + lc + j;
        d[0] = v.x * ATTN_SCALE; d[1] = v.y * ATTN_SCALE;
        d[2] = v.z * ATTN_SCALE; d[3] = v.w * ATTN_SCALE;
    }
    __syncthreads();
    unsigned qa[8][4];
    const int qr = warp * 16;
#pragma unroll
    for (int kc = 0; kc < 8; kc++) {
        qa[kc][0] = tf32u(Ks[(qr + g)     * 64 + kc * 8 + t]);
        qa[kc][1] = tf32u(Ks[(qr + 8 + g) * 64 + kc * 8 + t]);
        qa[kc][2] = tf32u(Ks[(qr + g)     * 64 + kc * 8 + t + 4]);
        qa[kc][3] = tf32u(Ks[(qr + 8 + g) * 64 + kc * 8 + t + 4]);
    }
    __syncthreads();

    float m0 = -1e30f, m1 = -1e30f, l0 = 0.f, l1 = 0.f;
    float o[8][4];
#pragma unroll
    for (int nt = 0; nt < 8; nt++)
#pragma unroll
        for (int i = 0; i < 4; i++) o[nt][i] = 0.f;

    for (int kt = 0; kt < SEQ / KT; kt++) {
        // ---- stage K, V (tf32 + swizzle) ----
        {
            const int swk = (lr & 7) << 2;
            const int swv = (lr & 7) << 3;
#pragma unroll
            for (int j = 0; j < 32; j += 4) {
                const int c = lc + j;
                float4 kv = *(const float4*)&Kb[((size_t)(kt * KT + lr)) * INNER + c];
                float* dk = Ks + lr * 64 + (c ^ swk);
                dk[0] = to_tf32(kv.x); dk[1] = to_tf32(kv.y);
                dk[2] = to_tf32(kv.z); dk[3] = to_tf32(kv.w);
                float4 vv = *(const float4*)&Vb[((size_t)(kt * KT + lr)) * INNER + c];
                float* dv = Vs + lr * 64 + (c ^ swv);
                dv[0] = to_tf32(vv.x); dv[1] = to_tf32(vv.y);
                dv[2] = to_tf32(vv.z); dv[3] = to_tf32(vv.w);
            }
        }
        __syncthreads();

        // ---- S = Q @ K^T : 16 n-tiles of 8 keys ----
        float s[16][4];
#pragma unroll
        for (int nt = 0; nt < 16; nt++) {
            s[nt][0] = s[nt][1] = s[nt][2] = s[nt][3] = 0.f;
            const int row = nt * 8 + g;
#pragma unroll
            for (int kc = 0; kc < 8; kc++) {
                unsigned b0 = __float_as_uint(Ks[row * 64 + ((kc * 8 + t)     ^ (g << 2))]);
                unsigned b1 = __float_as_uint(Ks[row * 64 + ((kc * 8 + t + 4) ^ (g << 2))]);
                mma_tf32(s[nt], qa[kc], b0, b1);
            }
        }

        // ---- online softmax (registers + quad shfl) ----
        float mx0 = -1e30f, mx1 = -1e30f;
#pragma unroll
        for (int nt = 0; nt < 16; nt++) {
            mx0 = fmaxf(mx0, fmaxf(s[nt][0], s[nt][1]));
            mx1 = fmaxf(mx1, fmaxf(s[nt][2], s[nt][3]));
        }
        mx0 = fmaxf(mx0, __shfl_xor_sync(0xffffffffu, mx0, 1));
        mx0 = fmaxf(mx0, __shfl_xor_sync(0xffffffffu, mx0, 2));
        mx1 = fmaxf(mx1, __shfl_xor_sync(0xffffffffu, mx1, 1));
        mx1 = fmaxf(mx1, __shfl_xor_sync(0xffffffffu, mx1, 2));
        const float mn0 = fmaxf(m0, mx0), mn1 = fmaxf(m1, mx1);
        const float a0 = __expf(m0 - mn0), a1 = __expf(m1 - mn1);
        m0 = mn0; m1 = mn1;

        float sum0 = 0.f, sum1 = 0.f;
#pragma unroll
        for (int nt = 0; nt < 16; nt++) {
            float p0 = __expf(s[nt][0] - mn0);
            float p1 = __expf(s[nt][1] - mn0);
            float p2 = __expf(s[nt][2] - mn1);
            float p3 = __expf(s[nt][3] - mn1);
            sum0 += p0 + p1; sum1 += p2 + p3;
            float2 lo; lo.x = to_tf32(p0); lo.y = to_tf32(p1);
            float2 hi; hi.x = to_tf32(p2); hi.y = to_tf32(p3);
            *(float2*)&Pw[(g)     * LDPW + nt * 8 + 2 * t] = lo;
            *(float2*)&Pw[(g + 8) * LDPW + nt * 8 + 2 * t] = hi;
        }
        sum0 += __shfl_xor_sync(0xffffffffu, sum0, 1);
        sum0 += __shfl_xor_sync(0xffffffffu, sum0, 2);
        sum1 += __shfl_xor_sync(0xffffffffu, sum1, 1);
        sum1 += __shfl_xor_sync(0xffffffffu, sum1, 2);
        l0 = l0 * a0 + sum0;
        l1 = l1 * a1 + sum1;

        // rescale O accumulators
#pragma unroll
        for (int nt = 0; nt < 8; nt++) {
            o[nt][0] *= a0; o[nt][1] *= a0;
            o[nt][2] *= a1; o[nt][3] *= a1;
        }
        __syncwarp();

        // ---- O += P @ V ----
#pragma unroll
        for (int kc = 0; kc < 16; kc++) {
            unsigned pa[4];
            pa[0] = __float_as_uint(Pw[(g)     * LDPW + kc * 8 + t]);
            pa[1] = __float_as_uint(Pw[(g + 8) * LDPW + kc * 8 + t]);
            pa[2] = __float_as_uint(Pw[(g)     * LDPW + kc * 8 + t + 4]);
            pa[3] = __float_as_uint(Pw[(g + 8) * LDPW + kc * 8 + t + 4]);
            const int r0 = kc * 8 + t, r1 = kc * 8 + t + 4;
#pragma unroll
            for (int nt = 0; nt < 8; nt++) {
                unsigned b0 = __float_as_uint(Vs[r0 * 64 + ((nt * 8 + g) ^ (t << 3))]);
                unsigned b1 = __float_as_uint(Vs[r1 * 64 + ((nt * 8 + g) ^ (t << 3) ^ 32)]);
                mma_tf32(o[nt], pa, b0, b1);
            }
        }
        __syncthreads();   // all warps done with Ks/Vs before next staging
    }

    // ---- epilogue ----
    const float i0 = 1.f / l0, i1 = 1.f / l1;
    float* Ob = O + ((size_t)(b * SEQ + qt * QT + qr)) * INNER + h * DHEAD;
#pragma unroll
    for (int nt = 0; nt < 8; nt++) {
        float2 lo; lo.x = o[nt][0] * i0; lo.y = o[nt][1] * i0;
        float2 hi; hi.x = o[nt][2] * i1; hi.y = o[nt][3] * i1;
        *(float2*)&Ob[(size_t)(g)     * INNER + nt * 8 + 2 * t] = lo;
        *(float2*)&Ob[(size_t)(g + 8) * INNER + nt * 8 + 2 * t] = hi;
    }
}

// ---------------------------------------------------------------------------
extern "C" void kernel_launch(void* const* d_in, const int* in_sizes, int n_in,
                              void* d_out, int out_size) {
    const float* x  = (const float*)d_in[0];
    const float* Wq = (const float*)d_in[1];
    const float* Wk = (const float*)d_in[2];
    const float* Wv = (const float*)d_in[3];
    const float* Wo = (const float*)d_in[4];
    const float* bo = (const float*)d_in[5];
    float* out = (float*)d_out;

    float *q, *k, *v, *a;
    cudaGetSymbolAddress((void**)&q, g_q);
    cudaGetSymbolAddress((void**)&k, g_k);
    cudaGetSymbolAddress((void**)&v, g_v);
    cudaGetSymbolAddress((void**)&a, g_a);

    const int attn_smem = (2 * 128 * 64 + 8 * 16 * LDPW) * (int)sizeof(float);
    cudaFuncSetAttribute(attn_fa2, cudaFuncAttributeMaxDynamicSharedMemorySize,
                         attn_smem);

    dim3 gproj(INNER / 128, MROWS / 128);
    gemm_tf32<<<gproj, 256>>>(x, Wq, q, MROWS, INNER, DIM);
    gemm_tf32<<<gproj, 256>>>(x, Wk, k, MROWS, INNER, DIM);
    gemm_tf32<<<gproj, 256>>>(x, Wv, v, MROWS, INNER, DIM);

    attn_fa2<<<dim3(SEQ / QT, NHEAD, BATCH), 256, attn_smem>>>(q, k, v, a);

    gemm_tf32<<<dim3(DIM / 128, MROWS / 128), 256>>>(a, Wo, out, MROWS, DIM, INNER);
    bias_add<<<(MROWS * DIM / 4) / 256, 256>>>(out, bo);
}

// round 5
// speedup vs baseline: 1.8857x; 1.0575x over previous
#include <cuda_runtime.h>
#include <cuda_bf16.h>
#include <mma.h>
#include <cstddef>

using namespace nvcuda;

#define DIM    1024
#define INNER  1024
#define NHEAD  16
#define DHEAD  64
#define BATCH  2
#define SEQ    2048
#define MROWS  (BATCH * SEQ)
#define ATTN_SCALE 0.125f

// Scratch (__device__ globals; no allocation allowed)
__device__ float g_q[MROWS * INNER];
__device__ float g_k[MROWS * INNER];
__device__ float g_v[MROWS * INNER];
__device__ float g_a[MROWS * INNER];
__device__ float g_rx[MROWS * DIM];      // tf32-rounded x
__device__ float g_rwq[DIM * INNER];
__device__ float g_rwk[DIM * INNER];
__device__ float g_rwv[DIM * INNER];
__device__ float g_rwo[INNER * DIM];

__device__ __forceinline__ float to_tf32(float x) {
    unsigned r;
    asm("cvt.rna.tf32.f32 %0, %1;" : "=r"(r) : "f"(x));
    return __uint_as_float(r);
}

__device__ __forceinline__ void cpa16(float* dst, const float* src) {
    unsigned d = (unsigned)__cvta_generic_to_shared(dst);
    asm volatile("cp.async.cg.shared.global [%0], [%1], 16;\n" :: "r"(d), "l"(src));
}
#define CP_COMMIT() asm volatile("cp.async.commit_group;\n" ::: "memory")
#define CP_WAIT0()  asm volatile("cp.async.wait_group 0;\n" ::: "memory")

__device__ __forceinline__ void mma_tf32(float c[4], const unsigned a[4],
                                         unsigned b0, unsigned b1) {
    asm volatile(
        "mma.sync.aligned.m16n8k8.row.col.f32.tf32.tf32.f32 "
        "{%0,%1,%2,%3}, {%4,%5,%6,%7}, {%8,%9}, {%0,%1,%2,%3};\n"
        : "+f"(c[0]), "+f"(c[1]), "+f"(c[2]), "+f"(c[3])
        : "r"(a[0]), "r"(a[1]), "r"(a[2]), "r"(a[3]), "r"(b0), "r"(b1));
}

typedef wmma::fragment<wmma::matrix_a, 16, 16, 8, wmma::precision::tf32, wmma::row_major> FragA;
typedef wmma::fragment<wmma::matrix_b, 16, 16, 8, wmma::precision::tf32, wmma::row_major> FragB;
typedef wmma::fragment<wmma::accumulator, 16, 16, 8, float> FragC;

// ---------------------------------------------------------------------------
// tf32 rounding prep
// ---------------------------------------------------------------------------
__global__ void round_tf32_k(float* __restrict__ d, const float* __restrict__ s, int n4) {
    int i = blockIdx.x * blockDim.x + threadIdx.x;
    if (i < n4) {
        float4 v = ((const float4*)s)[i];
        v.x = to_tf32(v.x); v.y = to_tf32(v.y);
        v.z = to_tf32(v.z); v.w = to_tf32(v.w);
        ((float4*)d)[i] = v;
    }
}

// ---------------------------------------------------------------------------
// tf32 GEMM, M=4096 N=1024 K=1024, 128x128 block, BK=32, cp.async 2-stage.
// Inputs pre-rounded tf32 (raw copy). blockIdx.z selects B/C (QKV fusion).
// ROUND: round outputs to tf32 in epilogue.
// ---------------------------------------------------------------------------
#define GAS (128 * 36)
#define GBS (32 * 132)
#define GSTG (GAS + GBS)

template <bool ROUND>
__global__ __launch_bounds__(256, 2)
void gemm_tc(const float* __restrict__ A,
             const float* __restrict__ B0, const float* __restrict__ B1,
             const float* __restrict__ B2,
             float* __restrict__ C0, float* __restrict__ C1, float* __restrict__ C2) {
    extern __shared__ float smg[];
    const int tid = threadIdx.x;
    const int warp = tid >> 5;
    const int wm = warp >> 1, wn = warp & 1;
    const int bx = blockIdx.x, by = blockIdx.y, bz = blockIdx.z;

    const float* B = bz == 0 ? B0 : (bz == 1 ? B1 : B2);
    float* C = bz == 0 ? C0 : (bz == 1 ? C1 : C2);

    const float* Ag = A + (size_t)(by * 128) * DIM;
    const float* Bg = B + bx * 128;

    const int arow = tid >> 1, acol = (tid & 1) * 16;
    const int brow = tid >> 3, bcol = (tid & 7) * 16;

    FragC acc[2][4];
#pragma unroll
    for (int mi = 0; mi < 2; mi++)
#pragma unroll
        for (int nf = 0; nf < 4; nf++) wmma::fill_fragment(acc[mi][nf], 0.f);

    // prologue stage k0=0 into buffer 0
    {
        float* As = smg; float* Bs = smg + GAS;
#pragma unroll
        for (int j = 0; j < 16; j += 4)
            cpa16(As + arow * 36 + acol + j, Ag + (size_t)arow * DIM + acol + j);
#pragma unroll
        for (int j = 0; j < 16; j += 4)
            cpa16(Bs + brow * 132 + bcol + j, Bg + (size_t)brow * INNER + bcol + j);
        CP_COMMIT();
    }

    for (int k0 = 0; k0 < DIM; k0 += 32) {
        CP_WAIT0();
        __syncthreads();
        if (k0 + 32 < DIM) {
            float* s = smg + (((k0 >> 5) + 1) & 1) * GSTG;
            float* As = s; float* Bs = s + GAS;
#pragma unroll
            for (int j = 0; j < 16; j += 4)
                cpa16(As + arow * 36 + acol + j,
                      Ag + (size_t)arow * DIM + k0 + 32 + acol + j);
#pragma unroll
            for (int j = 0; j < 16; j += 4)
                cpa16(Bs + brow * 132 + bcol + j,
                      Bg + (size_t)(k0 + 32 + brow) * INNER + bcol + j);
            CP_COMMIT();
        }
        float* As = smg + ((k0 >> 5) & 1) * GSTG;
        float* Bs = As + GAS;
#pragma unroll
        for (int kf = 0; kf < 4; kf++) {
            FragA a0, a1;
            wmma::load_matrix_sync(a0, As + (wm * 32) * 36 + kf * 8, 36);
            wmma::load_matrix_sync(a1, As + (wm * 32 + 16) * 36 + kf * 8, 36);
#pragma unroll
            for (int nf = 0; nf < 4; nf++) {
                FragB b;
                wmma::load_matrix_sync(b, Bs + (kf * 8) * 132 + wn * 64 + nf * 16, 132);
                wmma::mma_sync(acc[0][nf], a0, b, acc[0][nf]);
                wmma::mma_sync(acc[1][nf], a1, b, acc[1][nf]);
            }
        }
    }

#pragma unroll
    for (int mi = 0; mi < 2; mi++)
#pragma unroll
        for (int nf = 0; nf < 4; nf++) {
            if (ROUND) {
#pragma unroll
                for (int e = 0; e < acc[mi][nf].num_elements; e++)
                    acc[mi][nf].x[e] = to_tf32(acc[mi][nf].x[e]);
            }
            wmma::store_matrix_sync(
                C + (size_t)(by * 128 + wm * 32 + mi * 16) * INNER + bx * 128 + wn * 64 + nf * 16,
                acc[mi][nf], INNER, wmma::mem_row_major);
        }
}

__global__ void bias_add(float* __restrict__ out, const float* __restrict__ bo) {
    int i = blockIdx.x * blockDim.x + threadIdx.x;
    int c = (i & (DIM / 4 - 1)) * 4;
    float4 v = ((float4*)out)[i];
    v.x += bo[c + 0]; v.y += bo[c + 1]; v.z += bo[c + 2]; v.w += bo[c + 3];
    ((float4*)out)[i] = v;
}

// ---------------------------------------------------------------------------
// FlashAttention-2, raw mma tf32, cp.async double-buffered K/V, 1 sync/iter.
// Q/K/V are pre-rounded tf32 (gemm epilogue), so staging is a raw copy.
// ---------------------------------------------------------------------------
#define QT 128
#define KT 128
#define KTILE (128 * 64)
#define LDPW 132
#define PWSZ 2112           // 16*132 floats per warp (also holds 16x68 Q staging)
#define NT (SEQ / KT)

__device__ __forceinline__ void stage_kv(int kt, float* buf,
                                         const float* Kb, const float* Vb,
                                         int lr, int lc) {
    const size_t roff = (size_t)(kt * KT + lr) * INNER;
    const int swk = (lr & 7) << 2;
    const int swv = (lr & 7) << 3;
    float* kd = buf + lr * 64;
    float* vd = buf + KTILE + lr * 64;
#pragma unroll
    for (int j = 0; j < 32; j += 4) {
        const int c = lc + j;
        cpa16(kd + (c ^ swk), Kb + roff + c);
        cpa16(vd + (c ^ swv), Vb + roff + c);
    }
}

__global__ __launch_bounds__(256, 1)
void attn_fa2(const float* __restrict__ Q, const float* __restrict__ K,
              const float* __restrict__ V, float* __restrict__ O) {
    extern __shared__ float sm[];
    float* Ps = sm + 4 * KTILE;

    const int tid  = threadIdx.x;
    const int warp = tid >> 5;
    const int lane = tid & 31;
    const int g = lane >> 2;
    const int t = lane & 3;
    const int qt = blockIdx.x, h = blockIdx.y, b = blockIdx.z;

    const float* Qb = Q + ((size_t)(b * SEQ + qt * QT)) * INNER + h * DHEAD;
    const float* Kb = K + (size_t)b * SEQ * INNER + h * DHEAD;
    const float* Vb = V + (size_t)b * SEQ * INNER + h * DHEAD;
    float* Pw = Ps + warp * PWSZ;

    const int lr = tid >> 1;
    const int lc = (tid & 1) * 32;

    // prologue: async stage KV tile 0 into buffer 0
    stage_kv(0, sm, Kb, Vb, lr, lc);
    CP_COMMIT();

    // Q staging (warp-local: warp w owns rows 16w..16w+15 = its own lr range)
    {
        const int r = lr & 15;
#pragma unroll
        for (int j = 0; j < 32; j += 4) {
            float4 v = *(const float4*)&Qb[(size_t)lr * INNER + lc + j];
            float* d = Pw + r * 68 + lc + j;
            d[0] = v.x * ATTN_SCALE; d[1] = v.y * ATTN_SCALE;
            d[2] = v.z * ATTN_SCALE; d[3] = v.w * ATTN_SCALE;
        }
    }
    __syncwarp();
    unsigned qa[8][4];
#pragma unroll
    for (int kc = 0; kc < 8; kc++) {
        qa[kc][0] = __float_as_uint(Pw[(g)     * 68 + kc * 8 + t]);
        qa[kc][1] = __float_as_uint(Pw[(8 + g) * 68 + kc * 8 + t]);
        qa[kc][2] = __float_as_uint(Pw[(g)     * 68 + kc * 8 + t + 4]);
        qa[kc][3] = __float_as_uint(Pw[(8 + g) * 68 + kc * 8 + t + 4]);
    }
    __syncwarp();

    float m0 = -1e30f, m1 = -1e30f, l0 = 0.f, l1 = 0.f;
    float o[8][4];
#pragma unroll
    for (int nt = 0; nt < 8; nt++)
#pragma unroll
        for (int i = 0; i < 4; i++) o[nt][i] = 0.f;

    for (int kt = 0; kt < NT; kt++) {
        CP_WAIT0();
        __syncthreads();    // tile kt visible; all warps done with kt-1's buffers
        if (kt + 1 < NT) {
            stage_kv(kt + 1, sm + ((kt + 1) & 1) * 2 * KTILE, Kb, Vb, lr, lc);
            CP_COMMIT();
        }
        const float* Ks = sm + (kt & 1) * 2 * KTILE;
        const float* Vs = Ks + KTILE;

        // ---- S = Q @ K^T ----
        float s[16][4];
#pragma unroll
        for (int nt = 0; nt < 16; nt++) {
            s[nt][0] = s[nt][1] = s[nt][2] = s[nt][3] = 0.f;
            const int row = nt * 8 + g;
#pragma unroll
            for (int kc = 0; kc < 8; kc++) {
                unsigned b0 = __float_as_uint(Ks[row * 64 + ((kc * 8 + t)     ^ (g << 2))]);
                unsigned b1 = __float_as_uint(Ks[row * 64 + ((kc * 8 + t + 4) ^ (g << 2))]);
                mma_tf32(s[nt], qa[kc], b0, b1);
            }
        }

        // ---- online softmax ----
        float mx0 = -1e30f, mx1 = -1e30f;
#pragma unroll
        for (int nt = 0; nt < 16; nt++) {
            mx0 = fmaxf(mx0, fmaxf(s[nt][0], s[nt][1]));
            mx1 = fmaxf(mx1, fmaxf(s[nt][2], s[nt][3]));
        }
        mx0 = fmaxf(mx0, __shfl_xor_sync(0xffffffffu, mx0, 1));
        mx0 = fmaxf(mx0, __shfl_xor_sync(0xffffffffu, mx0, 2));
        mx1 = fmaxf(mx1, __shfl_xor_sync(0xffffffffu, mx1, 1));
        mx1 = fmaxf(mx1, __shfl_xor_sync(0xffffffffu, mx1, 2));
        const float mn0 = fmaxf(m0, mx0), mn1 = fmaxf(m1, mx1);
        const float a0 = __expf(m0 - mn0), a1 = __expf(m1 - mn1);
        m0 = mn0; m1 = mn1;

        float sum0 = 0.f, sum1 = 0.f;
#pragma unroll
        for (int nt = 0; nt < 16; nt++) {
            float p0 = __expf(s[nt][0] - mn0);
            float p1 = __expf(s[nt][1] - mn0);
            float p2 = __expf(s[nt][2] - mn1);
            float p3 = __expf(s[nt][3] - mn1);
            sum0 += p0 + p1; sum1 += p2 + p3;
            float2 lo; lo.x = to_tf32(p0); lo.y = to_tf32(p1);
            float2 hi; hi.x = to_tf32(p2); hi.y = to_tf32(p3);
            *(float2*)&Pw[(g)     * LDPW + nt * 8 + 2 * t] = lo;
            *(float2*)&Pw[(g + 8) * LDPW + nt * 8 + 2 * t] = hi;
        }
        sum0 += __shfl_xor_sync(0xffffffffu, sum0, 1);
        sum0 += __shfl_xor_sync(0xffffffffu, sum0, 2);
        sum1 += __shfl_xor_sync(0xffffffffu, sum1, 1);
        sum1 += __shfl_xor_sync(0xffffffffu, sum1, 2);
        l0 = l0 * a0 + sum0;
        l1 = l1 * a1 + sum1;

#pragma unroll
        for (int nt = 0; nt < 8; nt++) {
            o[nt][0] *= a0; o[nt][1] *= a0;
            o[nt][2] *= a1; o[nt][3] *= a1;
        }
        __syncwarp();

        // ---- O += P @ V ----
#pragma unroll
        for (int kc = 0; kc < 16; kc++) {
            unsigned pa[4];
            pa[0] = __float_as_uint(Pw[(g)     * LDPW + kc * 8 + t]);
            pa[1] = __float_as_uint(Pw[(g + 8) * LDPW + kc * 8 + t]);
            pa[2] = __float_as_uint(Pw[(g)     * LDPW + kc * 8 + t + 4]);
            pa[3] = __float_as_uint(Pw[(g + 8) * LDPW + kc * 8 + t + 4]);
            const int r0 = kc * 8 + t, r1 = kc * 8 + t + 4;
#pragma unroll
            for (int nt = 0; nt < 8; nt++) {
                unsigned b0 = __float_as_uint(Vs[r0 * 64 + ((nt * 8 + g) ^ (t << 3))]);
                unsigned b1 = __float_as_uint(Vs[r1 * 64 + ((nt * 8 + g) ^ (t << 3) ^ 32)]);
                mma_tf32(o[nt], pa, b0, b1);
            }
        }
    }

    // ---- epilogue (round to tf32 for the out-proj GEMM) ----
    const float i0 = 1.f / l0, i1 = 1.f / l1;
    const int qr = warp * 16;
    float* Ob = O + ((size_t)(b * SEQ + qt * QT + qr)) * INNER + h * DHEAD;
#pragma unroll
    for (int nt = 0; nt < 8; nt++) {
        float2 lo; lo.x = to_tf32(o[nt][0] * i0); lo.y = to_tf32(o[nt][1] * i0);
        float2 hi; hi.x = to_tf32(o[nt][2] * i1); hi.y = to_tf32(o[nt][3] * i1);
        *(float2*)&Ob[(size_t)(g)     * INNER + nt * 8 + 2 * t] = lo;
        *(float2*)&Ob[(size_t)(g + 8) * INNER + nt * 8 + 2 * t] = hi;
    }
}

// ---------------------------------------------------------------------------
extern "C" void kernel_launch(void* const* d_in, const int* in_sizes, int n_in,
                              void* d_out, int out_size) {
    const float* x  = (const float*)d_in[0];
    const float* Wq = (const float*)d_in[1];
    const float* Wk = (const float*)d_in[2];
    const float* Wv = (const float*)d_in[3];
    const float* Wo = (const float*)d_in[4];
    const float* bo = (const float*)d_in[5];
    float* out = (float*)d_out;

    float *q, *k, *v, *a, *rx, *rwq, *rwk, *rwv, *rwo;
    cudaGetSymbolAddress((void**)&q, g_q);
    cudaGetSymbolAddress((void**)&k, g_k);
    cudaGetSymbolAddress((void**)&v, g_v);
    cudaGetSymbolAddress((void**)&a, g_a);
    cudaGetSymbolAddress((void**)&rx, g_rx);
    cudaGetSymbolAddress((void**)&rwq, g_rwq);
    cudaGetSymbolAddress((void**)&rwk, g_rwk);
    cudaGetSymbolAddress((void**)&rwv, g_rwv);
    cudaGetSymbolAddress((void**)&rwo, g_rwo);

    const int gemm_smem = 2 * GSTG * (int)sizeof(float);
    const int attn_smem = (4 * KTILE + 8 * PWSZ) * (int)sizeof(float);
    cudaFuncSetAttribute(gemm_tc<true>,  cudaFuncAttributeMaxDynamicSharedMemorySize, gemm_smem);
    cudaFuncSetAttribute(gemm_tc<false>, cudaFuncAttributeMaxDynamicSharedMemorySize, gemm_smem);
    cudaFuncSetAttribute(attn_fa2, cudaFuncAttributeMaxDynamicSharedMemorySize, attn_smem);

    // prep: round inputs/weights to tf32
    round_tf32_k<<<(MROWS * DIM / 4 + 255) / 256, 256>>>(rx, x, MROWS * DIM / 4);
    round_tf32_k<<<(DIM * INNER / 4 + 255) / 256, 256>>>(rwq, Wq, DIM * INNER / 4);
    round_tf32_k<<<(DIM * INNER / 4 + 255) / 256, 256>>>(rwk, Wk, DIM * INNER / 4);
    round_tf32_k<<<(DIM * INNER / 4 + 255) / 256, 256>>>(rwv, Wv, DIM * INNER / 4);
    round_tf32_k<<<(INNER * DIM / 4 + 255) / 256, 256>>>(rwo, Wo, INNER * DIM / 4);

    // fused QKV projections (z = 0,1,2), outputs rounded to tf32
    gemm_tc<true><<<dim3(INNER / 128, MROWS / 128, 3), 256, gemm_smem>>>(
        rx, rwq, rwk, rwv, q, k, v);

    attn_fa2<<<dim3(SEQ / QT, NHEAD, BATCH), 256, attn_smem>>>(q, k, v, a);

    // output projection (a already tf32-rounded by attention epilogue)
    gemm_tc<false><<<dim3(DIM / 128, MROWS / 128, 1), 256, gemm_smem>>>(
        a, rwo, rwo, rwo, out, out, out);
    bias_add<<<(MROWS * DIM / 4) / 256, 256>>>(out, bo);
}

// round 6
// speedup vs baseline: 2.0721x; 1.0989x over previous
#include <cuda_runtime.h>
#include <cuda_bf16.h>
#include <mma.h>
#include <cstddef>

using namespace nvcuda;

#define DIM    1024
#define INNER  1024
#define NHEAD  16
#define DHEAD  64
#define BATCH  2
#define SEQ    2048
#define MROWS  (BATCH * SEQ)
#define ATTN_SCALE 0.125f

__device__ float g_q[MROWS * INNER];
__device__ float g_k[MROWS * INNER];
__device__ float g_v[MROWS * INNER];
__device__ float g_a[MROWS * INNER];
__device__ float g_rx[MROWS * DIM];
__device__ float g_rwq[DIM * INNER];
__device__ float g_rwk[DIM * INNER];
__device__ float g_rwv[DIM * INNER];
__device__ float g_rwo[INNER * DIM];

__device__ __forceinline__ float to_tf32(float x) {
    unsigned r;
    asm("cvt.rna.tf32.f32 %0, %1;" : "=r"(r) : "f"(x));
    return __uint_as_float(r);
}
__device__ __forceinline__ void cpa16(float* dst, const float* src) {
    unsigned d = (unsigned)__cvta_generic_to_shared(dst);
    asm volatile("cp.async.cg.shared.global [%0], [%1], 16;\n" :: "r"(d), "l"(src));
}
#define CP_COMMIT() asm volatile("cp.async.commit_group;\n" ::: "memory")
#define CP_WAIT0()  asm volatile("cp.async.wait_group 0;\n" ::: "memory")
#define CP_WAIT1()  asm volatile("cp.async.wait_group 1;\n" ::: "memory")

__device__ __forceinline__ void mma_tf32(float c[4], const unsigned a[4],
                                         unsigned b0, unsigned b1) {
    asm volatile(
        "mma.sync.aligned.m16n8k8.row.col.f32.tf32.tf32.f32 "
        "{%0,%1,%2,%3}, {%4,%5,%6,%7}, {%8,%9}, {%0,%1,%2,%3};\n"
        : "+f"(c[0]), "+f"(c[1]), "+f"(c[2]), "+f"(c[3])
        : "r"(a[0]), "r"(a[1]), "r"(a[2]), "r"(a[3]), "r"(b0), "r"(b1));
}

typedef wmma::fragment<wmma::matrix_a, 16, 16, 8, wmma::precision::tf32, wmma::row_major> FragA;
typedef wmma::fragment<wmma::matrix_b, 16, 16, 8, wmma::precision::tf32, wmma::row_major> FragB;
typedef wmma::fragment<wmma::accumulator, 16, 16, 8, float> FragC;

__global__ void round_tf32_k(float* __restrict__ d, const float* __restrict__ s, int n4) {
    int i = blockIdx.x * blockDim.x + threadIdx.x;
    if (i < n4) {
        float4 v = ((const float4*)s)[i];
        v.x = to_tf32(v.x); v.y = to_tf32(v.y);
        v.z = to_tf32(v.z); v.w = to_tf32(v.w);
        ((float4*)d)[i] = v;
    }
}

// ---------------------------------------------------------------------------
// tf32 GEMM, 128x128 block, BK=32, 3-stage cp.async pipeline, 2 CTAs/SM.
// ---------------------------------------------------------------------------
#define GAS (128 * 36)
#define GBS (32 * 132)
#define GSTG (GAS + GBS)
#define GNIT (DIM / 32)

template <bool ROUND>
__global__ __launch_bounds__(256, 2)
void gemm_tc(const float* __restrict__ A,
             const float* __restrict__ B0, const float* __restrict__ B1,
             const float* __restrict__ B2,
             float* __restrict__ C0, float* __restrict__ C1, float* __restrict__ C2) {
    extern __shared__ float smg[];
    const int tid = threadIdx.x;
    const int warp = tid >> 5;
    const int wm = warp >> 1, wn = warp & 1;
    const int bx = blockIdx.x, by = blockIdx.y, bz = blockIdx.z;

    const float* B = bz == 0 ? B0 : (bz == 1 ? B1 : B2);
    float* C = bz == 0 ? C0 : (bz == 1 ? C1 : C2);

    const float* Ag = A + (size_t)(by * 128) * DIM;
    const float* Bg = B + bx * 128;

    const int arow = tid >> 1, acol = (tid & 1) * 16;
    const int brow = tid >> 3, bcol = (tid & 7) * 16;

    FragC acc[2][4];
#pragma unroll
    for (int mi = 0; mi < 2; mi++)
#pragma unroll
        for (int nf = 0; nf < 4; nf++) wmma::fill_fragment(acc[mi][nf], 0.f);

    auto stage = [&](int k0, float* s) {
        float* As = s; float* Bs = s + GAS;
#pragma unroll
        for (int j = 0; j < 16; j += 4)
            cpa16(As + arow * 36 + acol + j, Ag + (size_t)arow * DIM + k0 + acol + j);
#pragma unroll
        for (int j = 0; j < 16; j += 4)
            cpa16(Bs + brow * 132 + bcol + j, Bg + (size_t)(k0 + brow) * INNER + bcol + j);
    };

    stage(0, smg);              CP_COMMIT();
    stage(32, smg + GSTG);      CP_COMMIT();

    for (int it = 0; it < GNIT; it++) {
        CP_WAIT1();
        __syncthreads();
        if (it + 2 < GNIT) stage((it + 2) * 32, smg + ((it + 2) % 3) * GSTG);
        CP_COMMIT();            // unconditional: keeps group counting exact
        float* As = smg + (it % 3) * GSTG;
        float* Bs = As + GAS;
#pragma unroll
        for (int kf = 0; kf < 4; kf++) {
            FragA a0, a1;
            wmma::load_matrix_sync(a0, As + (wm * 32) * 36 + kf * 8, 36);
            wmma::load_matrix_sync(a1, As + (wm * 32 + 16) * 36 + kf * 8, 36);
#pragma unroll
            for (int nf = 0; nf < 4; nf++) {
                FragB b;
                wmma::load_matrix_sync(b, Bs + (kf * 8) * 132 + wn * 64 + nf * 16, 132);
                wmma::mma_sync(acc[0][nf], a0, b, acc[0][nf]);
                wmma::mma_sync(acc[1][nf], a1, b, acc[1][nf]);
            }
        }
    }

#pragma unroll
    for (int mi = 0; mi < 2; mi++)
#pragma unroll
        for (int nf = 0; nf < 4; nf++) {
            if (ROUND) {
#pragma unroll
                for (int e = 0; e < acc[mi][nf].num_elements; e++)
                    acc[mi][nf].x[e] = to_tf32(acc[mi][nf].x[e]);
            }
            wmma::store_matrix_sync(
                C + (size_t)(by * 128 + wm * 32 + mi * 16) * INNER + bx * 128 + wn * 64 + nf * 16,
                acc[mi][nf], INNER, wmma::mem_row_major);
        }
}

__global__ void bias_add(float* __restrict__ out, const float* __restrict__ bo) {
    int i = blockIdx.x * blockDim.x + threadIdx.x;
    int c = (i & (DIM / 4 - 1)) * 4;
    float4 v = ((float4*)out)[i];
    v.x += bo[c + 0]; v.y += bo[c + 1]; v.z += bo[c + 2]; v.w += bo[c + 3];
    ((float4*)out)[i] = v;
}

// ---------------------------------------------------------------------------
// FlashAttention-2, tf32 mma, KT=64 (2 CTAs/SM), cp.async double buffer.
// ---------------------------------------------------------------------------
#define QT 128
#define KT 64
#define KV64 (64 * 64)          // floats per K (or V) tile
#define LDPW 68
#define PWSZ (16 * LDPW)
#define NT (SEQ / KT)

__device__ __forceinline__ void stage_kv(int kt, float* buf,
                                         const float* Kb, const float* Vb,
                                         int lr, int lc) {
    const size_t roff = (size_t)(kt * KT + lr) * INNER;
    const int swk = (lr & 7) << 2;
    const int swv = (lr & 7) << 3;
    float* kd = buf + lr * 64;
    float* vd = buf + KV64 + lr * 64;
#pragma unroll
    for (int j = 0; j < 16; j += 4) {
        const int c = lc + j;
        cpa16(kd + (c ^ swk), Kb + roff + c);
        cpa16(vd + (c ^ swv), Vb + roff + c);
    }
}

__global__ __launch_bounds__(256, 2)
void attn_fa2(const float* __restrict__ Q, const float* __restrict__ K,
              const float* __restrict__ V, float* __restrict__ O) {
    extern __shared__ float sm[];
    float* Ps = sm + 2 * 2 * KV64;   // after 2 stages of (K,V)

    const int tid  = threadIdx.x;
    const int warp = tid >> 5;
    const int lane = tid & 31;
    const int g = lane >> 2;
    const int t = lane & 3;
    const int qt = blockIdx.x, h = blockIdx.y, b = blockIdx.z;

    const float* Qb = Q + ((size_t)(b * SEQ + qt * QT)) * INNER + h * DHEAD;
    const float* Kb = K + (size_t)b * SEQ * INNER + h * DHEAD;
    const float* Vb = V + (size_t)b * SEQ * INNER + h * DHEAD;
    float* Pw = Ps + warp * PWSZ;

    const int klr = tid >> 2;          // 0..63  (KV staging row)
    const int klc = (tid & 3) * 16;    // 0,16,32,48
    const int qlr = tid >> 1;          // 0..127 (Q staging row)
    const int qlc = (tid & 1) * 32;

    stage_kv(0, sm, Kb, Vb, klr, klc);
    CP_COMMIT();

    // Q staging (warp-local rows) then pull A fragments once
    {
        const int r = qlr & 15;
#pragma unroll
        for (int j = 0; j < 32; j += 4) {
            float4 v = *(const float4*)&Qb[(size_t)qlr * INNER + qlc + j];
            float* d = Pw + r * LDPW + qlc + j;
            d[0] = v.x * ATTN_SCALE; d[1] = v.y * ATTN_SCALE;
            d[2] = v.z * ATTN_SCALE; d[3] = v.w * ATTN_SCALE;
        }
    }
    __syncwarp();
    unsigned qa[8][4];
#pragma unroll
    for (int kc = 0; kc < 8; kc++) {
        qa[kc][0] = __float_as_uint(Pw[(g)     * LDPW + kc * 8 + t]);
        qa[kc][1] = __float_as_uint(Pw[(8 + g) * LDPW + kc * 8 + t]);
        qa[kc][2] = __float_as_uint(Pw[(g)     * LDPW + kc * 8 + t + 4]);
        qa[kc][3] = __float_as_uint(Pw[(8 + g) * LDPW + kc * 8 + t + 4]);
    }
    __syncwarp();

    float m0 = -1e30f, m1 = -1e30f, l0 = 0.f, l1 = 0.f;
    float o[8][4];
#pragma unroll
    for (int nt = 0; nt < 8; nt++)
#pragma unroll
        for (int i = 0; i < 4; i++) o[nt][i] = 0.f;

    for (int kt = 0; kt < NT; kt++) {
        CP_WAIT0();
        __syncthreads();
        if (kt + 1 < NT)
            stage_kv(kt + 1, sm + ((kt + 1) & 1) * 2 * KV64, Kb, Vb, klr, klc);
        CP_COMMIT();
        const float* Ks = sm + (kt & 1) * 2 * KV64;
        const float* Vs = Ks + KV64;

        // ---- S = Q @ K^T (64 keys -> 8 n-tiles) ----
        float s[8][4];
#pragma unroll
        for (int nt = 0; nt < 8; nt++) {
            s[nt][0] = s[nt][1] = s[nt][2] = s[nt][3] = 0.f;
            const int row = nt * 8 + g;
#pragma unroll
            for (int kc = 0; kc < 8; kc++) {
                unsigned b0 = __float_as_uint(Ks[row * 64 + ((kc * 8 + t)     ^ (g << 2))]);
                unsigned b1 = __float_as_uint(Ks[row * 64 + ((kc * 8 + t + 4) ^ (g << 2))]);
                mma_tf32(s[nt], qa[kc], b0, b1);
            }
        }

        // ---- online softmax ----
        float mx0 = -1e30f, mx1 = -1e30f;
#pragma unroll
        for (int nt = 0; nt < 8; nt++) {
            mx0 = fmaxf(mx0, fmaxf(s[nt][0], s[nt][1]));
            mx1 = fmaxf(mx1, fmaxf(s[nt][2], s[nt][3]));
        }
        mx0 = fmaxf(mx0, __shfl_xor_sync(0xffffffffu, mx0, 1));
        mx0 = fmaxf(mx0, __shfl_xor_sync(0xffffffffu, mx0, 2));
        mx1 = fmaxf(mx1, __shfl_xor_sync(0xffffffffu, mx1, 1));
        mx1 = fmaxf(mx1, __shfl_xor_sync(0xffffffffu, mx1, 2));
        const float mn0 = fmaxf(m0, mx0), mn1 = fmaxf(m1, mx1);
        const float a0 = __expf(m0 - mn0), a1 = __expf(m1 - mn1);
        m0 = mn0; m1 = mn1;

        float sum0 = 0.f, sum1 = 0.f;
#pragma unroll
        for (int nt = 0; nt < 8; nt++) {
            float p0 = __expf(s[nt][0] - mn0);
            float p1 = __expf(s[nt][1] - mn0);
            float p2 = __expf(s[nt][2] - mn1);
            float p3 = __expf(s[nt][3] - mn1);
            sum0 += p0 + p1; sum1 += p2 + p3;
            float2 lo; lo.x = to_tf32(p0); lo.y = to_tf32(p1);
            float2 hi; hi.x = to_tf32(p2); hi.y = to_tf32(p3);
            *(float2*)&Pw[(g)     * LDPW + nt * 8 + 2 * t] = lo;
            *(float2*)&Pw[(g + 8) * LDPW + nt * 8 + 2 * t] = hi;
        }
        sum0 += __shfl_xor_sync(0xffffffffu, sum0, 1);
        sum0 += __shfl_xor_sync(0xffffffffu, sum0, 2);
        sum1 += __shfl_xor_sync(0xffffffffu, sum1, 1);
        sum1 += __shfl_xor_sync(0xffffffffu, sum1, 2);
        l0 = l0 * a0 + sum0;
        l1 = l1 * a1 + sum1;

#pragma unroll
        for (int nt = 0; nt < 8; nt++) {
            o[nt][0] *= a0; o[nt][1] *= a0;
            o[nt][2] *= a1; o[nt][3] *= a1;
        }
        __syncwarp();

        // ---- O += P @ V (64 keys -> 8 k-steps) ----
#pragma unroll
        for (int kc = 0; kc < 8; kc++) {
            unsigned pa[4];
            pa[0] = __float_as_uint(Pw[(g)     * LDPW + kc * 8 + t]);
            pa[1] = __float_as_uint(Pw[(g + 8) * LDPW + kc * 8 + t]);
            pa[2] = __float_as_uint(Pw[(g)     * LDPW + kc * 8 + t + 4]);
            pa[3] = __float_as_uint(Pw[(g + 8) * LDPW + kc * 8 + t + 4]);
            const int r0 = kc * 8 + t, r1 = kc * 8 + t + 4;
#pragma unroll
            for (int nt = 0; nt < 8; nt++) {
                unsigned b0 = __float_as_uint(Vs[r0 * 64 + ((nt * 8 + g) ^ (t << 3))]);
                unsigned b1 = __float_as_uint(Vs[r1 * 64 + ((nt * 8 + g) ^ (t << 3) ^ 32)]);
                mma_tf32(o[nt], pa, b0, b1);
            }
        }
    }

    // ---- epilogue ----
    const float i0 = 1.f / l0, i1 = 1.f / l1;
    const int qr = warp * 16;
    float* Ob = O + ((size_t)(b * SEQ + qt * QT + qr)) * INNER + h * DHEAD;
#pragma unroll
    for (int nt = 0; nt < 8; nt++) {
        float2 lo; lo.x = to_tf32(o[nt][0] * i0); lo.y = to_tf32(o[nt][1] * i0);
        float2 hi; hi.x = to_tf32(o[nt][2] * i1); hi.y = to_tf32(o[nt][3] * i1);
        *(float2*)&Ob[(size_t)(g)     * INNER + nt * 8 + 2 * t] = lo;
        *(float2*)&Ob[(size_t)(g + 8) * INNER + nt * 8 + 2 * t] = hi;
    }
}

// ---------------------------------------------------------------------------
extern "C" void kernel_launch(void* const* d_in, const int* in_sizes, int n_in,
                              void* d_out, int out_size) {
    const float* x  = (const float*)d_in[0];
    const float* Wq = (const float*)d_in[1];
    const float* Wk = (const float*)d_in[2];
    const float* Wv = (const float*)d_in[3];
    const float* Wo = (const float*)d_in[4];
    const float* bo = (const float*)d_in[5];
    float* out = (float*)d_out;

    float *q, *k, *v, *a, *rx, *rwq, *rwk, *rwv, *rwo;
    cudaGetSymbolAddress((void**)&q, g_q);
    cudaGetSymbolAddress((void**)&k, g_k);
    cudaGetSymbolAddress((void**)&v, g_v);
    cudaGetSymbolAddress((void**)&a, g_a);
    cudaGetSymbolAddress((void**)&rx, g_rx);
    cudaGetSymbolAddress((void**)&rwq, g_rwq);
    cudaGetSymbolAddress((void**)&rwk, g_rwk);
    cudaGetSymbolAddress((void**)&rwv, g_rwv);
    cudaGetSymbolAddress((void**)&rwo, g_rwo);

    const int gemm_smem = 3 * GSTG * (int)sizeof(float);
    const int attn_smem = (4 * KV64 + 8 * PWSZ) * (int)sizeof(float);
    cudaFuncSetAttribute(gemm_tc<true>,  cudaFuncAttributeMaxDynamicSharedMemorySize, gemm_smem);
    cudaFuncSetAttribute(gemm_tc<false>, cudaFuncAttributeMaxDynamicSharedMemorySize, gemm_smem);
    cudaFuncSetAttribute(attn_fa2, cudaFuncAttributeMaxDynamicSharedMemorySize, attn_smem);

    round_tf32_k<<<(MROWS * DIM / 4 + 255) / 256, 256>>>(rx, x, MROWS * DIM / 4);
    round_tf32_k<<<(DIM * INNER / 4 + 255) / 256, 256>>>(rwq, Wq, DIM * INNER / 4);
    round_tf32_k<<<(DIM * INNER / 4 + 255) / 256, 256>>>(rwk, Wk, DIM * INNER / 4);
    round_tf32_k<<<(DIM * INNER / 4 + 255) / 256, 256>>>(rwv, Wv, DIM * INNER / 4);
    round_tf32_k<<<(INNER * DIM / 4 + 255) / 256, 256>>>(rwo, Wo, INNER * DIM / 4);

    gemm_tc<true><<<dim3(INNER / 128, MROWS / 128, 3), 256, gemm_smem>>>(
        rx, rwq, rwk, rwv, q, k, v);

    attn_fa2<<<dim3(SEQ / QT, NHEAD, BATCH), 256, attn_smem>>>(q, k, v, a);

    gemm_tc<false><<<dim3(DIM / 128, MROWS / 128, 1), 256, gemm_smem>>>(
        a, rwo, rwo, rwo, out, out, out);
    bias_add<<<(MROWS * DIM / 4) / 256, 256>>>(out, bo);
}

// round 8
// speedup vs baseline: 6.0024x; 2.8968x over previous
#include <cuda_runtime.h>
#include <cuda_fp16.h>
#include <cstdint>
#include <cstddef>

#define DIM    1024
#define INNER  1024
#define NHEAD  16
#define DHEAD  64
#define BATCH  2
#define SEQ    2048
#define MROWS  (BATCH * SEQ)
#define ATTN_SCALE 0.125f

// Scratch (__device__ globals; allocation-free rule)
__device__ __half g_q[MROWS * INNER];
__device__ __half g_k[MROWS * INNER];
__device__ __half g_v[MROWS * INNER];
__device__ __half g_a[MROWS * INNER];
__device__ __half g_rx[MROWS * DIM];
__device__ __half g_rwq[DIM * INNER];   // K-major (transposed) fp16 weights
__device__ __half g_rwk[DIM * INNER];
__device__ __half g_rwv[DIM * INNER];
__device__ __half g_rwo[INNER * DIM];

__device__ __forceinline__ void cpa16(void* dst, const void* src) {
    unsigned d = (unsigned)__cvta_generic_to_shared(dst);
    asm volatile("cp.async.cg.shared.global [%0], [%1], 16;\n" :: "r"(d), "l"(src));
}
#define CP_COMMIT() asm volatile("cp.async.commit_group;\n" ::: "memory")
#define CP_WAIT0()  asm volatile("cp.async.wait_group 0;\n" ::: "memory")
#define CP_WAIT1()  asm volatile("cp.async.wait_group 1;\n" ::: "memory")

// D(f32) += A(f16) * B(f16): m16n8k16
__device__ __forceinline__ void mma_f16(float c[4], const unsigned a[4],
                                        unsigned b0, unsigned b1) {
    asm volatile(
        "mma.sync.aligned.m16n8k16.row.col.f32.f16.f16.f32 "
        "{%0,%1,%2,%3}, {%4,%5,%6,%7}, {%8,%9}, {%0,%1,%2,%3};\n"
        : "+f"(c[0]), "+f"(c[1]), "+f"(c[2]), "+f"(c[3])
        : "r"(a[0]), "r"(a[1]), "r"(a[2]), "r"(a[3]), "r"(b0), "r"(b1));
}
__device__ __forceinline__ void ldsm_x4_trans(unsigned& r0, unsigned& r1,
                                              unsigned& r2, unsigned& r3,
                                              unsigned addr) {
    asm volatile("ldmatrix.sync.aligned.m8n8.x4.trans.shared.b16 {%0,%1,%2,%3}, [%4];"
                 : "=r"(r0), "=r"(r1), "=r"(r2), "=r"(r3) : "r"(addr));
}
__device__ __forceinline__ unsigned packh2(float a, float b) {
    __half2 h = __floats2half2_rn(a, b);
    return *(unsigned*)&h;
}

// ---------------------------------------------------------------------------
// prep: fp32 -> fp16
// ---------------------------------------------------------------------------
__global__ void to_half_k(__half* __restrict__ d, const float* __restrict__ s, int n4) {
    int i = blockIdx.x * blockDim.x + threadIdx.x;
    if (i < n4) {
        float4 v = ((const float4*)s)[i];
        ((__half2*)d)[2 * i]     = __floats2half2_rn(v.x, v.y);
        ((__half2*)d)[2 * i + 1] = __floats2half2_rn(v.z, v.w);
    }
}
// dst[n][k] = (half)src[k][n], 1024x1024
__global__ void transpose_half(__half* __restrict__ dst, const float* __restrict__ src) {
    __shared__ float tile[32][33];
    const int bx = blockIdx.x * 32, by = blockIdx.y * 32;
    const int tx = threadIdx.x, ty = threadIdx.y;
#pragma unroll
    for (int i = 0; i < 32; i += 8)
        tile[ty + i][tx] = src[(size_t)(by + ty + i) * 1024 + bx + tx];
    __syncthreads();
#pragma unroll
    for (int i = 0; i < 32; i += 8)
        dst[(size_t)(bx + ty + i) * 1024 + by + tx] = __float2half(tile[tx][ty + i]);
}

// ---------------------------------------------------------------------------
// fp16 GEMM: C[M,1024] = A[M,1024] @ Bt^T, Bt K-major [n][k].
// 128x128 tile, BK=32, 3-stage cp.async, 256 thr, warp tile 32x64.
// Smem rows: 32 halves + 8 pad = 80B; 4-byte pair reads conflict-free.
// OUT_FP32: float C + bias; else half C, Q-scale on bz==0.
// ---------------------------------------------------------------------------
#define GLD 80
#define GOPB (128 * GLD)
#define GSTGB (2 * GOPB)
#define GEMM_SMEM (3 * GSTGB)

template <bool OUT_FP32>
__global__ __launch_bounds__(256, 2)
void gemm_f16(const __half* __restrict__ A,
              const __half* __restrict__ B0, const __half* __restrict__ B1,
              const __half* __restrict__ B2,
              void* C0, void* C1, void* C2, const float* __restrict__ bo) {
    extern __shared__ char smg[];
    const int tid = threadIdx.x;
    const int warp = tid >> 5;
    const int lane = tid & 31;
    const int g = lane >> 2, t = lane & 3;
    const int wm = warp >> 1, wn = warp & 1;
    const int bx = blockIdx.x, by = blockIdx.y, bz = blockIdx.z;

    const __half* Bt = bz == 0 ? B0 : (bz == 1 ? B1 : B2);
    void* Cp = bz == 0 ? C0 : (bz == 1 ? C1 : C2);

    const __half* Ag = A + (size_t)(by * 128) * DIM;
    const __half* Bg = Bt + (size_t)(bx * 128) * DIM;

    float acc[2][8][4];
#pragma unroll
    for (int mt = 0; mt < 2; mt++)
#pragma unroll
        for (int nt = 0; nt < 8; nt++)
#pragma unroll
            for (int i = 0; i < 4; i++) acc[mt][nt][i] = 0.f;

    const int sr = tid >> 1;            // 0..127
    const int sc = (tid & 1) * 2;       // chunk base (2 chunks of 16B each)

    auto stage = [&](int k0, char* s) {
        char* sA = s;
        char* sB = s + GOPB;
#pragma unroll
        for (int c = 0; c < 2; c++) {
            int ch = sc + c;
            cpa16(sA + sr * GLD + ch * 16, Ag + (size_t)sr * DIM + k0 + ch * 8);
            cpa16(sB + sr * GLD + ch * 16, Bg + (size_t)sr * DIM + k0 + ch * 8);
        }
    };

    stage(0, smg);              CP_COMMIT();
    stage(32, smg + GSTGB);     CP_COMMIT();

    for (int it = 0; it < 32; it++) {
        CP_WAIT1();
        __syncthreads();
        if (it + 2 < 32) stage((it + 2) * 32, smg + ((it + 2) % 3) * GSTGB);
        CP_COMMIT();
        const char* sA = smg + (it % 3) * GSTGB;
        const char* sB = sA + GOPB;
#pragma unroll
        for (int kc = 0; kc < 2; kc++) {
            unsigned a[2][4];
#pragma unroll
            for (int mt = 0; mt < 2; mt++) {
                const char* ab = sA + (wm * 32 + mt * 16) * GLD + kc * 32 + 4 * t;
                a[mt][0] = *(const unsigned*)(ab + g * GLD);
                a[mt][1] = *(const unsigned*)(ab + (g + 8) * GLD);
                a[mt][2] = *(const unsigned*)(ab + g * GLD + 16);
                a[mt][3] = *(const unsigned*)(ab + (g + 8) * GLD + 16);
            }
#pragma unroll
            for (int nt = 0; nt < 8; nt++) {
                const char* bb = sB + (wn * 64 + nt * 8 + g) * GLD + kc * 32 + 4 * t;
                unsigned b0 = *(const unsigned*)bb;
                unsigned b1 = *(const unsigned*)(bb + 16);
                mma_f16(acc[0][nt], a[0], b0, b1);
                mma_f16(acc[1][nt], a[1], b0, b1);
            }
        }
    }

    const float qsc = (!OUT_FP32 && bz == 0) ? ATTN_SCALE : 1.f;
#pragma unroll
    for (int mt = 0; mt < 2; mt++) {
#pragma unroll
        for (int nt = 0; nt < 8; nt++) {
            const int row = by * 128 + wm * 32 + mt * 16;
            const int col = bx * 128 + wn * 64 + nt * 8 + 2 * t;
            if (OUT_FP32) {
                float* C = (float*)Cp;
                float2 v0, v1;
                v0.x = acc[mt][nt][0] + bo[col];
                v0.y = acc[mt][nt][1] + bo[col + 1];
                v1.x = acc[mt][nt][2] + bo[col];
                v1.y = acc[mt][nt][3] + bo[col + 1];
                *(float2*)&C[(size_t)(row + g) * 1024 + col] = v0;
                *(float2*)&C[(size_t)(row + 8 + g) * 1024 + col] = v1;
            } else {
                __half* C = (__half*)Cp;
                *(unsigned*)&C[(size_t)(row + g) * 1024 + col] =
                    packh2(acc[mt][nt][0] * qsc, acc[mt][nt][1] * qsc);
                *(unsigned*)&C[(size_t)(row + 8 + g) * 1024 + col] =
                    packh2(acc[mt][nt][2] * qsc, acc[mt][nt][3] * qsc);
            }
        }
    }
}

// ---------------------------------------------------------------------------
// FlashAttention-2, fp16 mma m16n8k16. CTA = (b,h,128-q tile), 8 warps,
// KT=64 keys/tile, 3-stage cp.async KV, Q staged via cp.async.
// K/V/Q smem rows 128B with 16B-granular XOR swizzle (off ^ (row&7)<<4).
// ---------------------------------------------------------------------------
#define KT 64
#define KVT_B (64 * 128)            // bytes per K (or V) tile
#define STG_B (2 * KVT_B)
#define QS_OFF (3 * STG_B)          // Q tile: 128 rows x 128B
#define P_OFF (QS_OFF + 128 * 128)
#define LDP 144                     // bytes per P row (64 halves + 8 pad)
#define PW_B (16 * LDP)
#define ATTN_SMEM (P_OFF + 8 * PW_B)
#define NT (SEQ / KT)

__global__ __launch_bounds__(256, 2)
void attn_fa2(const __half* __restrict__ Q, const __half* __restrict__ K,
              const __half* __restrict__ V, __half* __restrict__ O) {
    extern __shared__ char sm[];
    const int tid  = threadIdx.x;
    const int warp = tid >> 5;
    const int lane = tid & 31;
    const int g = lane >> 2, t = lane & 3;
    const int qt = blockIdx.x, h = blockIdx.y, b = blockIdx.z;

    const __half* Qb = Q + ((size_t)(b * SEQ + qt * 128)) * INNER + h * DHEAD;
    const __half* Kb = K + (size_t)b * SEQ * INNER + h * DHEAD;
    const __half* Vb = V + (size_t)b * SEQ * INNER + h * DHEAD;
    char* Pw = sm + P_OFF + warp * PW_B;

    auto stage_kv = [&](int kt, char* buf) {
        const int r = tid >> 2;             // 0..63
        const int j0 = (tid & 3) * 2;
        const size_t go = (size_t)(kt * KT + r) * INNER;
#pragma unroll
        for (int c = 0; c < 2; c++) {
            int j = j0 + c;
            unsigned off = (unsigned)(r * 128 + ((j * 16) ^ ((r & 7) << 4)));
            cpa16(buf + off, Kb + go + j * 8);
            cpa16(buf + KVT_B + off, Vb + go + j * 8);
        }
    };

    // prologue: Q + KV0 in group 0, KV1 in group 1
    {
        const int r = tid >> 1;             // 0..127
        const int j0 = (tid & 1) * 4;
#pragma unroll
        for (int c = 0; c < 4; c++) {
            int j = j0 + c;
            unsigned off = (unsigned)(r * 128 + ((j * 16) ^ ((r & 7) << 4)));
            cpa16(sm + QS_OFF + off, Qb + (size_t)r * INNER + j * 8);
        }
    }
    stage_kv(0, sm);            CP_COMMIT();
    stage_kv(1, sm + STG_B);    CP_COMMIT();

    unsigned qa[4][4];
    float m0 = -1e30f, m1 = -1e30f, l0 = 0.f, l1 = 0.f;
    float o[8][4];
#pragma unroll
    for (int nt = 0; nt < 8; nt++)
#pragma unroll
        for (int i = 0; i < 4; i++) o[nt][i] = 0.f;

    const int qr = warp * 16;
    for (int kt = 0; kt < NT; kt++) {
        CP_WAIT1();
        __syncthreads();
        if (kt + 2 < NT) stage_kv(kt + 2, sm + ((kt + 2) % 3) * STG_B);
        CP_COMMIT();

        if (kt == 0) {
            // pull Q fragments (Q pre-scaled by 0.125 in projection epilogue)
            const char* Qs = sm + QS_OFF;
            const unsigned sw = (unsigned)(g << 4);
#pragma unroll
            for (int kc = 0; kc < 4; kc++) {
                const unsigned c0 = ((unsigned)(kc * 32) ^ sw) + 4 * t;
                const unsigned c1 = ((unsigned)(kc * 32 + 16) ^ sw) + 4 * t;
                qa[kc][0] = *(const unsigned*)(Qs + (qr + g) * 128 + c0);
                qa[kc][1] = *(const unsigned*)(Qs + (qr + 8 + g) * 128 + c0);
                qa[kc][2] = *(const unsigned*)(Qs + (qr + g) * 128 + c1);
                qa[kc][3] = *(const unsigned*)(Qs + (qr + 8 + g) * 128 + c1);
            }
        }
        const char* Ks = sm + (kt % 3) * STG_B;
        const char* Vs = Ks + KVT_B;

        // ---- S = Q @ K^T ----
        float s[8][4];
        const unsigned sw = (unsigned)(g << 4);
#pragma unroll
        for (int nt = 0; nt < 8; nt++) {
            s[nt][0] = s[nt][1] = s[nt][2] = s[nt][3] = 0.f;
            const char* kb = Ks + (nt * 8 + g) * 128;
#pragma unroll
            for (int kc = 0; kc < 4; kc++) {
                unsigned b0 = *(const unsigned*)(kb + (((unsigned)(kc * 32) ^ sw) + 4 * t));
                unsigned b1 = *(const unsigned*)(kb + (((unsigned)(kc * 32 + 16) ^ sw) + 4 * t));
                mma_f16(s[nt], qa[kc], b0, b1);
            }
        }

        // ---- online softmax ----
        float mx0 = -1e30f, mx1 = -1e30f;
#pragma unroll
        for (int nt = 0; nt < 8; nt++) {
            mx0 = fmaxf(mx0, fmaxf(s[nt][0], s[nt][1]));
            mx1 = fmaxf(mx1, fmaxf(s[nt][2], s[nt][3]));
        }
        mx0 = fmaxf(mx0, __shfl_xor_sync(0xffffffffu, mx0, 1));
        mx0 = fmaxf(mx0, __shfl_xor_sync(0xffffffffu, mx0, 2));
        mx1 = fmaxf(mx1, __shfl_xor_sync(0xffffffffu, mx1, 1));
        mx1 = fmaxf(mx1, __shfl_xor_sync(0xffffffffu, mx1, 2));
        const float mn0 = fmaxf(m0, mx0), mn1 = fmaxf(m1, mx1);
        const float a0 = __expf(m0 - mn0), a1 = __expf(m1 - mn1);
        m0 = mn0; m1 = mn1;

        float sum0 = 0.f, sum1 = 0.f;
#pragma unroll
        for (int nt = 0; nt < 8; nt++) {
            float p0 = __expf(s[nt][0] - mn0);
            float p1 = __expf(s[nt][1] - mn0);
            float p2 = __expf(s[nt][2] - mn1);
            float p3 = __expf(s[nt][3] - mn1);
            sum0 += p0 + p1; sum1 += p2 + p3;
            *(unsigned*)(Pw + g * LDP + nt * 16 + 4 * t) = packh2(p0, p1);
            *(unsigned*)(Pw + (g + 8) * LDP + nt * 16 + 4 * t) = packh2(p2, p3);
        }
        sum0 += __shfl_xor_sync(0xffffffffu, sum0, 1);
        sum0 += __shfl_xor_sync(0xffffffffu, sum0, 2);
        sum1 += __shfl_xor_sync(0xffffffffu, sum1, 1);
        sum1 += __shfl_xor_sync(0xffffffffu, sum1, 2);
        l0 = l0 * a0 + sum0;
        l1 = l1 * a1 + sum1;

#pragma unroll
        for (int nt = 0; nt < 8; nt++) {
            o[nt][0] *= a0; o[nt][1] *= a0;
            o[nt][2] *= a1; o[nt][3] *= a1;
        }
        __syncwarp();

        // ---- O += P @ V ----
        const unsigned VsU = (unsigned)__cvta_generic_to_shared(Vs);
        const int midx = lane >> 3, mr = lane & 7;
#pragma unroll
        for (int kc = 0; kc < 4; kc++) {
            unsigned pa[4];
            pa[0] = *(const unsigned*)(Pw + g * LDP + kc * 32 + 4 * t);
            pa[1] = *(const unsigned*)(Pw + (g + 8) * LDP + kc * 32 + 4 * t);
            pa[2] = *(const unsigned*)(Pw + g * LDP + kc * 32 + 16 + 4 * t);
            pa[3] = *(const unsigned*)(Pw + (g + 8) * LDP + kc * 32 + 16 + 4 * t);
#pragma unroll
            for (int ntp = 0; ntp < 4; ntp++) {
                const int nt = ntp * 2 + (midx >> 1);
                const int key = kc * 16 + (midx & 1) * 8 + mr;
                unsigned addr = VsU + (unsigned)(key * 128 + ((nt * 16) ^ ((key & 7) << 4)));
                unsigned r0, r1, r2, r3;
                ldsm_x4_trans(r0, r1, r2, r3, addr);
                mma_f16(o[ntp * 2], pa, r0, r1);
                mma_f16(o[ntp * 2 + 1], pa, r2, r3);
            }
        }
    }

    // ---- epilogue: fp16 output for out-projection ----
    const float i0 = 1.f / l0, i1 = 1.f / l1;
    __half* Ob = O + ((size_t)(b * SEQ + qt * 128 + qr)) * INNER + h * DHEAD;
#pragma unroll
    for (int nt = 0; nt < 8; nt++) {
        *(unsigned*)&Ob[(size_t)g * INNER + nt * 8 + 2 * t] =
            packh2(o[nt][0] * i0, o[nt][1] * i0);
        *(unsigned*)&Ob[(size_t)(g + 8) * INNER + nt * 8 + 2 * t] =
            packh2(o[nt][2] * i1, o[nt][3] * i1);
    }
}

// ---------------------------------------------------------------------------
extern "C" void kernel_launch(void* const* d_in, const int* in_sizes, int n_in,
                              void* d_out, int out_size) {
    const float* x  = (const float*)d_in[0];
    const float* Wq = (const float*)d_in[1];
    const float* Wk = (const float*)d_in[2];
    const float* Wv = (const float*)d_in[3];
    const float* Wo = (const float*)d_in[4];
    const float* bo = (const float*)d_in[5];
    float* out = (float*)d_out;

    __half *q, *k, *v, *a, *rx, *rwq, *rwk, *rwv, *rwo;
    cudaGetSymbolAddress((void**)&q, g_q);
    cudaGetSymbolAddress((void**)&k, g_k);
    cudaGetSymbolAddress((void**)&v, g_v);
    cudaGetSymbolAddress((void**)&a, g_a);
    cudaGetSymbolAddress((void**)&rx, g_rx);
    cudaGetSymbolAddress((void**)&rwq, g_rwq);
    cudaGetSymbolAddress((void**)&rwk, g_rwk);
    cudaGetSymbolAddress((void**)&rwv, g_rwv);
    cudaGetSymbolAddress((void**)&rwo, g_rwo);

    cudaFuncSetAttribute((const void*)gemm_f16<false>,
                         cudaFuncAttributeMaxDynamicSharedMemorySize, GEMM_SMEM);
    cudaFuncSetAttribute((const void*)gemm_f16<true>,
                         cudaFuncAttributeMaxDynamicSharedMemorySize, GEMM_SMEM);
    cudaFuncSetAttribute((const void*)attn_fa2,
                         cudaFuncAttributeMaxDynamicSharedMemorySize, ATTN_SMEM);

    to_half_k<<<(MROWS * DIM / 4 + 255) / 256, 256>>>(rx, x, MROWS * DIM / 4);
    dim3 tb(32, 8), tg(32, 32);
    transpose_half<<<tg, tb>>>(rwq, Wq);
    transpose_half<<<tg, tb>>>(rwk, Wk);
    transpose_half<<<tg, tb>>>(rwv, Wv);
    transpose_half<<<tg, tb>>>(rwo, Wo);

    gemm_f16<false><<<dim3(INNER / 128, MROWS / 128, 3), 256, GEMM_SMEM>>>(
        rx, rwq, rwk, rwv, q, k, v, nullptr);

    attn_fa2<<<dim3(SEQ / 128, NHEAD, BATCH), 256, ATTN_SMEM>>>(q, k, v, a);

    gemm_f16<true><<<dim3(DIM / 128, MROWS / 128, 1), 256, GEMM_SMEM>>>(
        a, rwo, rwo, rwo, out, out, out, bo);
}

// round 9
// speedup vs baseline: 6.8203x; 1.1363x over previous
#include <cuda_runtime.h>
#include <cuda_fp16.h>
#include <cstdint>
#include <cstddef>

#define DIM    1024
#define INNER  1024
#define NHEAD  16
#define DHEAD  64
#define BATCH  2
#define SEQ    2048
#define MROWS  (BATCH * SEQ)
#define ATTN_SCALE 0.125f
#define L2E 1.4426950408889634f

// Scratch (__device__ globals; allocation-free rule)
__device__ __half g_q[MROWS * INNER];
__device__ __half g_k[MROWS * INNER];
__device__ __half g_v[MROWS * INNER];
__device__ __half g_a[MROWS * INNER];
__device__ __half g_rx[MROWS * DIM];
__device__ __half g_rwq[DIM * INNER];   // K-major (transposed) fp16 weights
__device__ __half g_rwk[DIM * INNER];
__device__ __half g_rwv[DIM * INNER];
__device__ __half g_rwo[INNER * DIM];

__device__ __forceinline__ void cpa16(void* dst, const void* src) {
    unsigned d = (unsigned)__cvta_generic_to_shared(dst);
    asm volatile("cp.async.cg.shared.global [%0], [%1], 16;\n" :: "r"(d), "l"(src));
}
#define CP_COMMIT() asm volatile("cp.async.commit_group;\n" ::: "memory")
#define CP_WAIT1()  asm volatile("cp.async.wait_group 1;\n" ::: "memory")

__device__ __forceinline__ void mma_f16(float c[4], const unsigned a[4],
                                        unsigned b0, unsigned b1) {
    asm volatile(
        "mma.sync.aligned.m16n8k16.row.col.f32.f16.f16.f32 "
        "{%0,%1,%2,%3}, {%4,%5,%6,%7}, {%8,%9}, {%0,%1,%2,%3};\n"
        : "+f"(c[0]), "+f"(c[1]), "+f"(c[2]), "+f"(c[3])
        : "r"(a[0]), "r"(a[1]), "r"(a[2]), "r"(a[3]), "r"(b0), "r"(b1));
}
__device__ __forceinline__ void ldsm_x4(unsigned& r0, unsigned& r1,
                                        unsigned& r2, unsigned& r3, unsigned addr) {
    asm volatile("ldmatrix.sync.aligned.m8n8.x4.shared.b16 {%0,%1,%2,%3}, [%4];"
                 : "=r"(r0), "=r"(r1), "=r"(r2), "=r"(r3) : "r"(addr));
}
__device__ __forceinline__ void ldsm_x4_trans(unsigned& r0, unsigned& r1,
                                              unsigned& r2, unsigned& r3,
                                              unsigned addr) {
    asm volatile("ldmatrix.sync.aligned.m8n8.x4.trans.shared.b16 {%0,%1,%2,%3}, [%4];"
                 : "=r"(r0), "=r"(r1), "=r"(r2), "=r"(r3) : "r"(addr));
}
__device__ __forceinline__ unsigned packh2(float a, float b) {
    __half2 h = __floats2half2_rn(a, b);
    return *(unsigned*)&h;
}
__device__ __forceinline__ unsigned h2exp2(unsigned y) {
    unsigned p;
    asm("ex2.approx.f16x2 %0, %1;" : "=r"(p) : "r"(y));
    return p;
}

// ---------------------------------------------------------------------------
// prep
// ---------------------------------------------------------------------------
__global__ void to_half_k(__half* __restrict__ d, const float* __restrict__ s, int n4) {
    int i = blockIdx.x * blockDim.x + threadIdx.x;
    if (i < n4) {
        float4 v = ((const float4*)s)[i];
        ((__half2*)d)[2 * i]     = __floats2half2_rn(v.x, v.y);
        ((__half2*)d)[2 * i + 1] = __floats2half2_rn(v.z, v.w);
    }
}
// dst[n][k] = (half)src[k][n], 1024x1024; z selects which weight
__global__ void transpose_half4(__half* w0, __half* w1, __half* w2, __half* w3,
                                const float* s0, const float* s1,
                                const float* s2, const float* s3) {
    __shared__ float tile[32][33];
    const int z = blockIdx.z;
    const float* src = z == 0 ? s0 : (z == 1 ? s1 : (z == 2 ? s2 : s3));
    __half* dst = z == 0 ? w0 : (z == 1 ? w1 : (z == 2 ? w2 : w3));
    const int bx = blockIdx.x * 32, by = blockIdx.y * 32;
    const int tx = threadIdx.x, ty = threadIdx.y;
#pragma unroll
    for (int i = 0; i < 32; i += 8)
        tile[ty + i][tx] = src[(size_t)(by + ty + i) * 1024 + bx + tx];
    __syncthreads();
#pragma unroll
    for (int i = 0; i < 32; i += 8)
        dst[(size_t)(bx + ty + i) * 1024 + by + tx] = __float2half(tile[tx][ty + i]);
}

// ---------------------------------------------------------------------------
// fp16 GEMM: C[M,1024] = A[M,1024] @ Bt^T (Bt K-major). 128x128, BK=32,
// 3-stage cp.async, ldmatrix fragment loads. OUT_FP32: fp32 C + bias.
// ---------------------------------------------------------------------------
#define GLD 80
#define GOPB (128 * GLD)
#define GSTGB (2 * GOPB)
#define GEMM_SMEM (3 * GSTGB)

template <bool OUT_FP32>
__global__ __launch_bounds__(256, 2)
void gemm_f16(const __half* __restrict__ A,
              const __half* __restrict__ B0, const __half* __restrict__ B1,
              const __half* __restrict__ B2,
              void* C0, void* C1, void* C2, const float* __restrict__ bo) {
    extern __shared__ char smg[];
    const int tid = threadIdx.x;
    const int warp = tid >> 5;
    const int lane = tid & 31;
    const int g = lane >> 2, t = lane & 3;
    const int l8 = lane >> 3, l7 = lane & 7;
    const int wm = warp >> 1, wn = warp & 1;
    const int bx = blockIdx.x, by = blockIdx.y, bz = blockIdx.z;

    const __half* Bt = bz == 0 ? B0 : (bz == 1 ? B1 : B2);
    void* Cp = bz == 0 ? C0 : (bz == 1 ? C1 : C2);

    const __half* Ag = A + (size_t)(by * 128) * DIM;
    const __half* Bg = Bt + (size_t)(bx * 128) * DIM;

    float acc[2][8][4];
#pragma unroll
    for (int mt = 0; mt < 2; mt++)
#pragma unroll
        for (int nt = 0; nt < 8; nt++)
#pragma unroll
            for (int i = 0; i < 4; i++) acc[mt][nt][i] = 0.f;

    const int sr = tid >> 1;
    const int sc = (tid & 1) * 2;

    auto stage = [&](int k0, char* s) {
        char* sA = s;
        char* sB = s + GOPB;
#pragma unroll
        for (int c = 0; c < 2; c++) {
            int ch = sc + c;
            cpa16(sA + sr * GLD + ch * 16, Ag + (size_t)sr * DIM + k0 + ch * 8);
            cpa16(sB + sr * GLD + ch * 16, Bg + (size_t)sr * DIM + k0 + ch * 8);
        }
    };

    stage(0, smg);              CP_COMMIT();
    stage(32, smg + GSTGB);     CP_COMMIT();

    // ldmatrix lane addressing
    const int a_r = ((l8 & 1) << 3) + l7;        // row within 16
    const int a_c = (l8 >> 1) << 4;              // 0 or 16 (k half)
    const int b_r = ((l8 >> 1) << 3) + l7;       // row within 16 (2 n-tiles)
    const int b_c = (l8 & 1) << 4;

    for (int it = 0; it < 32; it++) {
        CP_WAIT1();
        __syncthreads();
        if (it + 2 < 32) stage((it + 2) * 32, smg + ((it + 2) % 3) * GSTGB);
        CP_COMMIT();
        const unsigned sAu = (unsigned)__cvta_generic_to_shared(smg + (it % 3) * GSTGB);
        const unsigned sBu = sAu + GOPB;
#pragma unroll
        for (int kc = 0; kc < 2; kc++) {
            unsigned a[2][4];
#pragma unroll
            for (int mt = 0; mt < 2; mt++)
                ldsm_x4(a[mt][0], a[mt][1], a[mt][2], a[mt][3],
                        sAu + (wm * 32 + mt * 16 + a_r) * GLD + kc * 32 + a_c);
#pragma unroll
            for (int ntp = 0; ntp < 4; ntp++) {
                unsigned b0, b1, b2, b3;
                ldsm_x4(b0, b1, b2, b3,
                        sBu + (wn * 64 + ntp * 16 + b_r) * GLD + kc * 32 + b_c);
                mma_f16(acc[0][ntp * 2], a[0], b0, b1);
                mma_f16(acc[1][ntp * 2], a[1], b0, b1);
                mma_f16(acc[0][ntp * 2 + 1], a[0], b2, b3);
                mma_f16(acc[1][ntp * 2 + 1], a[1], b2, b3);
            }
        }
    }

    const float qsc = (!OUT_FP32 && bz == 0) ? ATTN_SCALE : 1.f;
#pragma unroll
    for (int mt = 0; mt < 2; mt++) {
#pragma unroll
        for (int nt = 0; nt < 8; nt++) {
            const int row = by * 128 + wm * 32 + mt * 16;
            const int col = bx * 128 + wn * 64 + nt * 8 + 2 * t;
            if (OUT_FP32) {
                float* C = (float*)Cp;
                float2 v0, v1;
                v0.x = acc[mt][nt][0] + bo[col];
                v0.y = acc[mt][nt][1] + bo[col + 1];
                v1.x = acc[mt][nt][2] + bo[col];
                v1.y = acc[mt][nt][3] + bo[col + 1];
                *(float2*)&C[(size_t)(row + g) * 1024 + col] = v0;
                *(float2*)&C[(size_t)(row + 8 + g) * 1024 + col] = v1;
            } else {
                __half* C = (__half*)Cp;
                *(unsigned*)&C[(size_t)(row + g) * 1024 + col] =
                    packh2(acc[mt][nt][0] * qsc, acc[mt][nt][1] * qsc);
                *(unsigned*)&C[(size_t)(row + 8 + g) * 1024 + col] =
                    packh2(acc[mt][nt][2] * qsc, acc[mt][nt][3] * qsc);
            }
        }
    }
}

// ---------------------------------------------------------------------------
// FlashAttention-2 fp16. KT=64, 3-stage cp.async, ldmatrix frags,
// f16x2 exp2 softmax. m state kept in log2 units (ml = m * log2e).
// ---------------------------------------------------------------------------
#define KT 64
#define KVT_B (64 * 128)
#define STG_B (2 * KVT_B)
#define QS_OFF (3 * STG_B)
#define P_OFF (QS_OFF + 128 * 128)
#define LDP 144
#define PW_B (16 * LDP)
#define ATTN_SMEM (P_OFF + 8 * PW_B)
#define NT (SEQ / KT)

__global__ __launch_bounds__(256, 2)
void attn_fa2(const __half* __restrict__ Q, const __half* __restrict__ K,
              const __half* __restrict__ V, __half* __restrict__ O) {
    extern __shared__ char sm[];
    const int tid  = threadIdx.x;
    const int warp = tid >> 5;
    const int lane = tid & 31;
    const int g = lane >> 2, t = lane & 3;
    const int l8 = lane >> 3, l7 = lane & 7;
    const int qt = blockIdx.x, h = blockIdx.y, b = blockIdx.z;

    const __half* Qb = Q + ((size_t)(b * SEQ + qt * 128)) * INNER + h * DHEAD;
    const __half* Kb = K + (size_t)b * SEQ * INNER + h * DHEAD;
    const __half* Vb = V + (size_t)b * SEQ * INNER + h * DHEAD;
    char* Pw = sm + P_OFF + warp * PW_B;
    const unsigned PwU = (unsigned)__cvta_generic_to_shared(Pw);

    auto stage_kv = [&](int kt, char* buf) {
        const int r = tid >> 2;
        const int j0 = (tid & 3) * 2;
        const size_t go = (size_t)(kt * KT + r) * INNER;
#pragma unroll
        for (int c = 0; c < 2; c++) {
            int j = j0 + c;
            unsigned off = (unsigned)(r * 128 + ((j * 16) ^ ((r & 7) << 4)));
            cpa16(buf + off, Kb + go + j * 8);
            cpa16(buf + KVT_B + off, Vb + go + j * 8);
        }
    };

    {
        const int r = tid >> 1;
        const int j0 = (tid & 1) * 4;
#pragma unroll
        for (int c = 0; c < 4; c++) {
            int j = j0 + c;
            unsigned off = (unsigned)(r * 128 + ((j * 16) ^ ((r & 7) << 4)));
            cpa16(sm + QS_OFF + off, Qb + (size_t)r * INNER + j * 8);
        }
    }
    stage_kv(0, sm);            CP_COMMIT();
    stage_kv(1, sm + STG_B);    CP_COMMIT();

    unsigned qa[4][4];
    float ml0 = -1e30f, ml1 = -1e30f, l0 = 0.f, l1 = 0.f;   // ml in log2 units
    float o[8][4];
#pragma unroll
    for (int nt = 0; nt < 8; nt++)
#pragma unroll
        for (int i = 0; i < 4; i++) o[nt][i] = 0.f;

    const int qr = warp * 16;
    for (int kt = 0; kt < NT; kt++) {
        CP_WAIT1();
        __syncthreads();
        if (kt + 2 < NT) stage_kv(kt + 2, sm + ((kt + 2) % 3) * STG_B);
        CP_COMMIT();

        if (kt == 0) {
            const char* Qs = sm + QS_OFF;
            const unsigned sw = (unsigned)(g << 4);
#pragma unroll
            for (int kc = 0; kc < 4; kc++) {
                const unsigned c0 = ((unsigned)(kc * 32) ^ sw) + 4 * t;
                const unsigned c1 = ((unsigned)(kc * 32 + 16) ^ sw) + 4 * t;
                qa[kc][0] = *(const unsigned*)(Qs + (qr + g) * 128 + c0);
                qa[kc][1] = *(const unsigned*)(Qs + (qr + 8 + g) * 128 + c0);
                qa[kc][2] = *(const unsigned*)(Qs + (qr + g) * 128 + c1);
                qa[kc][3] = *(const unsigned*)(Qs + (qr + 8 + g) * 128 + c1);
            }
        }
        const char* Ks = sm + (kt % 3) * STG_B;
        const char* Vs = Ks + KVT_B;
        const unsigned KsU = (unsigned)__cvta_generic_to_shared(Ks);

        // ---- S = Q @ K^T : K-frags via ldmatrix.x4 (2 n-tiles per load) ----
        float s[8][4];
#pragma unroll
        for (int nt = 0; nt < 8; nt++)
            s[nt][0] = s[nt][1] = s[nt][2] = s[nt][3] = 0.f;
#pragma unroll
        for (int kc = 0; kc < 4; kc++) {
#pragma unroll
            for (int ntp = 0; ntp < 4; ntp++) {
                const int krow = ntp * 16 + ((l8 >> 1) << 3) + l7;
                const int kch = kc * 2 + (l8 & 1);
                unsigned addr = KsU + (unsigned)(krow * 128 +
                                   ((kch * 16) ^ ((krow & 7) << 4)));
                unsigned b0, b1, b2, b3;
                ldsm_x4(b0, b1, b2, b3, addr);
                mma_f16(s[ntp * 2], qa[kc], b0, b1);
                mma_f16(s[ntp * 2 + 1], qa[kc], b2, b3);
            }
        }

        // ---- online softmax (f16x2 exp2; m tracked in log2 units) ----
        float mx0 = -1e30f, mx1 = -1e30f;
#pragma unroll
        for (int nt = 0; nt < 8; nt++) {
            mx0 = fmaxf(mx0, fmaxf(s[nt][0], s[nt][1]));
            mx1 = fmaxf(mx1, fmaxf(s[nt][2], s[nt][3]));
        }
        mx0 = fmaxf(mx0, __shfl_xor_sync(0xffffffffu, mx0, 1));
        mx0 = fmaxf(mx0, __shfl_xor_sync(0xffffffffu, mx0, 2));
        mx1 = fmaxf(mx1, __shfl_xor_sync(0xffffffffu, mx1, 1));
        mx1 = fmaxf(mx1, __shfl_xor_sync(0xffffffffu, mx1, 2));
        const float mnl0 = fmaxf(ml0, mx0 * L2E), mnl1 = fmaxf(ml1, mx1 * L2E);
        const float a0 = exp2f(ml0 - mnl0), a1 = exp2f(ml1 - mnl1);
        ml0 = mnl0; ml1 = mnl1;

        float sum0 = 0.f, sum1 = 0.f;
#pragma unroll
        for (int nt = 0; nt < 8; nt++) {
            float y0 = fmaf(s[nt][0], L2E, -mnl0);
            float y1 = fmaf(s[nt][1], L2E, -mnl0);
            float y2 = fmaf(s[nt][2], L2E, -mnl1);
            float y3 = fmaf(s[nt][3], L2E, -mnl1);
            unsigned p01 = h2exp2(packh2(y0, y1));
            unsigned p23 = h2exp2(packh2(y2, y3));
            *(unsigned*)(Pw + g * LDP + nt * 16 + 4 * t) = p01;
            *(unsigned*)(Pw + (g + 8) * LDP + nt * 16 + 4 * t) = p23;
            float2 f01 = __half22float2(*(__half2*)&p01);
            float2 f23 = __half22float2(*(__half2*)&p23);
            sum0 += f01.x + f01.y;
            sum1 += f23.x + f23.y;
        }
        sum0 += __shfl_xor_sync(0xffffffffu, sum0, 1);
        sum0 += __shfl_xor_sync(0xffffffffu, sum0, 2);
        sum1 += __shfl_xor_sync(0xffffffffu, sum1, 1);
        sum1 += __shfl_xor_sync(0xffffffffu, sum1, 2);
        l0 = l0 * a0 + sum0;
        l1 = l1 * a1 + sum1;

#pragma unroll
        for (int nt = 0; nt < 8; nt++) {
            o[nt][0] *= a0; o[nt][1] *= a0;
            o[nt][2] *= a1; o[nt][3] *= a1;
        }
        __syncwarp();

        // ---- O += P @ V : P via ldmatrix.x4, V via ldmatrix.x4.trans ----
        const unsigned VsU = (unsigned)__cvta_generic_to_shared(Vs);
        const int midx = lane >> 3, mr = lane & 7;
#pragma unroll
        for (int kc = 0; kc < 4; kc++) {
            unsigned pa[4];
            ldsm_x4(pa[0], pa[1], pa[2], pa[3],
                    PwU + (unsigned)((((l8 & 1) << 3) + l7) * LDP +
                                     kc * 32 + ((l8 >> 1) << 4)));
#pragma unroll
            for (int ntp = 0; ntp < 4; ntp++) {
                const int nt = ntp * 2 + (midx >> 1);
                const int key = kc * 16 + (midx & 1) * 8 + mr;
                unsigned addr = VsU + (unsigned)(key * 128 + ((nt * 16) ^ ((key & 7) << 4)));
                unsigned r0, r1, r2, r3;
                ldsm_x4_trans(r0, r1, r2, r3, addr);
                mma_f16(o[ntp * 2], pa, r0, r1);
                mma_f16(o[ntp * 2 + 1], pa, r2, r3);
            }
        }
    }

    // ---- epilogue: fp16 output ----
    const float i0 = 1.f / l0, i1 = 1.f / l1;
    __half* Ob = O + ((size_t)(b * SEQ + qt * 128 + qr)) * INNER + h * DHEAD;
#pragma unroll
    for (int nt = 0; nt < 8; nt++) {
        *(unsigned*)&Ob[(size_t)g * INNER + nt * 8 + 2 * t] =
            packh2(o[nt][0] * i0, o[nt][1] * i0);
        *(unsigned*)&Ob[(size_t)(g + 8) * INNER + nt * 8 + 2 * t] =
            packh2(o[nt][2] * i1, o[nt][3] * i1);
    }
}

// ---------------------------------------------------------------------------
extern "C" void kernel_launch(void* const* d_in, const int* in_sizes, int n_in,
                              void* d_out, int out_size) {
    const float* x  = (const float*)d_in[0];
    const float* Wq = (const float*)d_in[1];
    const float* Wk = (const float*)d_in[2];
    const float* Wv = (const float*)d_in[3];
    const float* Wo = (const float*)d_in[4];
    const float* bo = (const float*)d_in[5];
    float* out = (float*)d_out;

    __half *q, *k, *v, *a, *rx, *rwq, *rwk, *rwv, *rwo;
    cudaGetSymbolAddress((void**)&q, g_q);
    cudaGetSymbolAddress((void**)&k, g_k);
    cudaGetSymbolAddress((void**)&v, g_v);
    cudaGetSymbolAddress((void**)&a, g_a);
    cudaGetSymbolAddress((void**)&rx, g_rx);
    cudaGetSymbolAddress((void**)&rwq, g_rwq);
    cudaGetSymbolAddress((void**)&rwk, g_rwk);
    cudaGetSymbolAddress((void**)&rwv, g_rwv);
    cudaGetSymbolAddress((void**)&rwo, g_rwo);

    cudaFuncSetAttribute((const void*)gemm_f16<false>,
                         cudaFuncAttributeMaxDynamicSharedMemorySize, GEMM_SMEM);
    cudaFuncSetAttribute((const void*)gemm_f16<true>,
                         cudaFuncAttributeMaxDynamicSharedMemorySize, GEMM_SMEM);
    cudaFuncSetAttribute((const void*)attn_fa2,
                         cudaFuncAttributeMaxDynamicSharedMemorySize, ATTN_SMEM);

    to_half_k<<<(MROWS * DIM / 4 + 255) / 256, 256>>>(rx, x, MROWS * DIM / 4);
    transpose_half4<<<dim3(32, 32, 4), dim3(32, 8)>>>(rwq, rwk, rwv, rwo,
                                                      Wq, Wk, Wv, Wo);

    gemm_f16<false><<<dim3(INNER / 128, MROWS / 128, 3), 256, GEMM_SMEM>>>(
        rx, rwq, rwk, rwv, q, k, v, nullptr);

    attn_fa2<<<dim3(SEQ / 128, NHEAD, BATCH), 256, ATTN_SMEM>>>(q, k, v, a);

    gemm_f16<true><<<dim3(DIM / 128, MROWS / 128, 1), 256, GEMM_SMEM>>>(
        a, rwo, rwo, rwo, out, out, out, bo);
}

// round 10
// speedup vs baseline: 7.0848x; 1.0388x over previous
#include <cuda_runtime.h>
#include <cuda_fp16.h>
#include <cstdint>
#include <cstddef>

#define DIM    1024
#define INNER  1024
#define NHEAD  16
#define DHEAD  64
#define BATCH  2
#define SEQ    2048
#define MROWS  (BATCH * SEQ)
#define ATTN_SCALE 0.125f
#define L2E 1.4426950408889634f

// Scratch (__device__ globals; allocation-free rule)
__device__ __half g_q[MROWS * INNER];
__device__ __half g_k[MROWS * INNER];
__device__ __half g_v[MROWS * INNER];
__device__ __half g_a[MROWS * INNER];
__device__ __half g_rx[MROWS * DIM];
__device__ __half g_rwq[DIM * INNER];   // K-major (transposed) fp16 weights
__device__ __half g_rwk[DIM * INNER];
__device__ __half g_rwv[DIM * INNER];
__device__ __half g_rwo[INNER * DIM];

__device__ __forceinline__ void cpa16(void* dst, const void* src) {
    unsigned d = (unsigned)__cvta_generic_to_shared(dst);
    asm volatile("cp.async.cg.shared.global [%0], [%1], 16;\n" :: "r"(d), "l"(src));
}
#define CP_COMMIT() asm volatile("cp.async.commit_group;\n" ::: "memory")
#define CP_WAIT0()  asm volatile("cp.async.wait_group 0;\n" ::: "memory")
#define CP_WAIT1()  asm volatile("cp.async.wait_group 1;\n" ::: "memory")

__device__ __forceinline__ void mma_f16(float c[4], const unsigned a[4],
                                        unsigned b0, unsigned b1) {
    asm volatile(
        "mma.sync.aligned.m16n8k16.row.col.f32.f16.f16.f32 "
        "{%0,%1,%2,%3}, {%4,%5,%6,%7}, {%8,%9}, {%0,%1,%2,%3};\n"
        : "+f"(c[0]), "+f"(c[1]), "+f"(c[2]), "+f"(c[3])
        : "r"(a[0]), "r"(a[1]), "r"(a[2]), "r"(a[3]), "r"(b0), "r"(b1));
}
__device__ __forceinline__ void ldsm_x4(unsigned& r0, unsigned& r1,
                                        unsigned& r2, unsigned& r3, unsigned addr) {
    asm volatile("ldmatrix.sync.aligned.m8n8.x4.shared.b16 {%0,%1,%2,%3}, [%4];"
                 : "=r"(r0), "=r"(r1), "=r"(r2), "=r"(r3) : "r"(addr));
}
__device__ __forceinline__ void ldsm_x4_trans(unsigned& r0, unsigned& r1,
                                              unsigned& r2, unsigned& r3,
                                              unsigned addr) {
    asm volatile("ldmatrix.sync.aligned.m8n8.x4.trans.shared.b16 {%0,%1,%2,%3}, [%4];"
                 : "=r"(r0), "=r"(r1), "=r"(r2), "=r"(r3) : "r"(addr));
}
__device__ __forceinline__ unsigned packh2(float a, float b) {
    __half2 h = __floats2half2_rn(a, b);
    return *(unsigned*)&h;
}
__device__ __forceinline__ unsigned h2exp2(unsigned y) {
    unsigned p;
    asm("ex2.approx.f16x2 %0, %1;" : "=r"(p) : "r"(y));
    return p;
}

// ---------------------------------------------------------------------------
// prep
// ---------------------------------------------------------------------------
__global__ void to_half_k(__half* __restrict__ d, const float* __restrict__ s, int n4) {
    int i = blockIdx.x * blockDim.x + threadIdx.x;
    if (i < n4) {
        float4 v = ((const float4*)s)[i];
        ((__half2*)d)[2 * i]     = __floats2half2_rn(v.x, v.y);
        ((__half2*)d)[2 * i + 1] = __floats2half2_rn(v.z, v.w);
    }
}
__global__ void transpose_half4(__half* w0, __half* w1, __half* w2, __half* w3,
                                const float* s0, const float* s1,
                                const float* s2, const float* s3) {
    __shared__ float tile[32][33];
    const int z = blockIdx.z;
    const float* src = z == 0 ? s0 : (z == 1 ? s1 : (z == 2 ? s2 : s3));
    __half* dst = z == 0 ? w0 : (z == 1 ? w1 : (z == 2 ? w2 : w3));
    const int bx = blockIdx.x * 32, by = blockIdx.y * 32;
    const int tx = threadIdx.x, ty = threadIdx.y;
#pragma unroll
    for (int i = 0; i < 32; i += 8)
        tile[ty + i][tx] = src[(size_t)(by + ty + i) * 1024 + bx + tx];
    __syncthreads();
#pragma unroll
    for (int i = 0; i < 32; i += 8)
        dst[(size_t)(bx + ty + i) * 1024 + by + tx] = __float2half(tile[tx][ty + i]);
}

// ---------------------------------------------------------------------------
// fp16 GEMM (unchanged from R9): 128x128, BK=32, 3-stage cp.async, ldmatrix.
// ---------------------------------------------------------------------------
#define GLD 80
#define GOPB (128 * GLD)
#define GSTGB (2 * GOPB)
#define GEMM_SMEM (3 * GSTGB)

template <bool OUT_FP32>
__global__ __launch_bounds__(256, 2)
void gemm_f16(const __half* __restrict__ A,
              const __half* __restrict__ B0, const __half* __restrict__ B1,
              const __half* __restrict__ B2,
              void* C0, void* C1, void* C2, const float* __restrict__ bo) {
    extern __shared__ char smg[];
    const int tid = threadIdx.x;
    const int warp = tid >> 5;
    const int lane = tid & 31;
    const int g = lane >> 2, t = lane & 3;
    const int l8 = lane >> 3, l7 = lane & 7;
    const int wm = warp >> 1, wn = warp & 1;
    const int bx = blockIdx.x, by = blockIdx.y, bz = blockIdx.z;

    const __half* Bt = bz == 0 ? B0 : (bz == 1 ? B1 : B2);
    void* Cp = bz == 0 ? C0 : (bz == 1 ? C1 : C2);

    const __half* Ag = A + (size_t)(by * 128) * DIM;
    const __half* Bg = Bt + (size_t)(bx * 128) * DIM;

    float acc[2][8][4];
#pragma unroll
    for (int mt = 0; mt < 2; mt++)
#pragma unroll
        for (int nt = 0; nt < 8; nt++)
#pragma unroll
            for (int i = 0; i < 4; i++) acc[mt][nt][i] = 0.f;

    const int sr = tid >> 1;
    const int sc = (tid & 1) * 2;

    auto stage = [&](int k0, char* s) {
        char* sA = s;
        char* sB = s + GOPB;
#pragma unroll
        for (int c = 0; c < 2; c++) {
            int ch = sc + c;
            cpa16(sA + sr * GLD + ch * 16, Ag + (size_t)sr * DIM + k0 + ch * 8);
            cpa16(sB + sr * GLD + ch * 16, Bg + (size_t)sr * DIM + k0 + ch * 8);
        }
    };

    stage(0, smg);              CP_COMMIT();
    stage(32, smg + GSTGB);     CP_COMMIT();

    const int a_r = ((l8 & 1) << 3) + l7;
    const int a_c = (l8 >> 1) << 4;
    const int b_r = ((l8 >> 1) << 3) + l7;
    const int b_c = (l8 & 1) << 4;

    for (int it = 0; it < 32; it++) {
        CP_WAIT1();
        __syncthreads();
        if (it + 2 < 32) stage((it + 2) * 32, smg + ((it + 2) % 3) * GSTGB);
        CP_COMMIT();
        const unsigned sAu = (unsigned)__cvta_generic_to_shared(smg + (it % 3) * GSTGB);
        const unsigned sBu = sAu + GOPB;
#pragma unroll
        for (int kc = 0; kc < 2; kc++) {
            unsigned a[2][4];
#pragma unroll
            for (int mt = 0; mt < 2; mt++)
                ldsm_x4(a[mt][0], a[mt][1], a[mt][2], a[mt][3],
                        sAu + (wm * 32 + mt * 16 + a_r) * GLD + kc * 32 + a_c);
#pragma unroll
            for (int ntp = 0; ntp < 4; ntp++) {
                unsigned b0, b1, b2, b3;
                ldsm_x4(b0, b1, b2, b3,
                        sBu + (wn * 64 + ntp * 16 + b_r) * GLD + kc * 32 + b_c);
                mma_f16(acc[0][ntp * 2], a[0], b0, b1);
                mma_f16(acc[1][ntp * 2], a[1], b0, b1);
                mma_f16(acc[0][ntp * 2 + 1], a[0], b2, b3);
                mma_f16(acc[1][ntp * 2 + 1], a[1], b2, b3);
            }
        }
    }

    const float qsc = (!OUT_FP32 && bz == 0) ? ATTN_SCALE : 1.f;
#pragma unroll
    for (int mt = 0; mt < 2; mt++) {
#pragma unroll
        for (int nt = 0; nt < 8; nt++) {
            const int row = by * 128 + wm * 32 + mt * 16;
            const int col = bx * 128 + wn * 64 + nt * 8 + 2 * t;
            if (OUT_FP32) {
                float* C = (float*)Cp;
                float2 v0, v1;
                v0.x = acc[mt][nt][0] + bo[col];
                v0.y = acc[mt][nt][1] + bo[col + 1];
                v1.x = acc[mt][nt][2] + bo[col];
                v1.y = acc[mt][nt][3] + bo[col + 1];
                *(float2*)&C[(size_t)(row + g) * 1024 + col] = v0;
                *(float2*)&C[(size_t)(row + 8 + g) * 1024 + col] = v1;
            } else {
                __half* C = (__half*)Cp;
                *(unsigned*)&C[(size_t)(row + g) * 1024 + col] =
                    packh2(acc[mt][nt][0] * qsc, acc[mt][nt][1] * qsc);
                *(unsigned*)&C[(size_t)(row + 8 + g) * 1024 + col] =
                    packh2(acc[mt][nt][2] * qsc, acc[mt][nt][3] * qsc);
            }
        }
    }
}

// ---------------------------------------------------------------------------
// FlashAttention-2 fp16, software-pipelined: S(kt+1) computed between
// softmax(kt) and PV(kt). Deferred l-reduction (quad shfl once, at end).
// ---------------------------------------------------------------------------
#define KT 64
#define KVT_B (64 * 128)
#define STG_B (2 * KVT_B)
#define QS_OFF (3 * STG_B)
#define P_OFF (QS_OFF + 128 * 128)
#define LDP 144
#define PW_B (16 * LDP)
#define ATTN_SMEM (P_OFF + 8 * PW_B)
#define NT (SEQ / KT)

__global__ __launch_bounds__(256, 2)
void attn_fa2(const __half* __restrict__ Q, const __half* __restrict__ K,
              const __half* __restrict__ V, __half* __restrict__ O) {
    extern __shared__ char sm[];
    const int tid  = threadIdx.x;
    const int warp = tid >> 5;
    const int lane = tid & 31;
    const int g = lane >> 2, t = lane & 3;
    const int l8 = lane >> 3, l7 = lane & 7;
    const int qt = blockIdx.x, h = blockIdx.y, b = blockIdx.z;

    const __half* Qb = Q + ((size_t)(b * SEQ + qt * 128)) * INNER + h * DHEAD;
    const __half* Kb = K + (size_t)b * SEQ * INNER + h * DHEAD;
    const __half* Vb = V + (size_t)b * SEQ * INNER + h * DHEAD;
    char* Pw = sm + P_OFF + warp * PW_B;
    const unsigned PwU = (unsigned)__cvta_generic_to_shared(Pw);

    auto stage_kv = [&](int kt, char* buf) {
        const int r = tid >> 2;
        const int j0 = (tid & 3) * 2;
        const size_t go = (size_t)(kt * KT + r) * INNER;
#pragma unroll
        for (int c = 0; c < 2; c++) {
            int j = j0 + c;
            unsigned off = (unsigned)(r * 128 + ((j * 16) ^ ((r & 7) << 4)));
            cpa16(buf + off, Kb + go + j * 8);
            cpa16(buf + KVT_B + off, Vb + go + j * 8);
        }
    };

    // prologue: Q + KV0 (group 0), KV1 (group 1)
    {
        const int r = tid >> 1;
        const int j0 = (tid & 1) * 4;
#pragma unroll
        for (int c = 0; c < 4; c++) {
            int j = j0 + c;
            unsigned off = (unsigned)(r * 128 + ((j * 16) ^ ((r & 7) << 4)));
            cpa16(sm + QS_OFF + off, Qb + (size_t)r * INNER + j * 8);
        }
    }
    stage_kv(0, sm);            CP_COMMIT();
    stage_kv(1, sm + STG_B);    CP_COMMIT();

    const int qr = warp * 16;
    CP_WAIT0();
    __syncthreads();

    // Q fragments
    unsigned qa[4][4];
    {
        const char* Qs = sm + QS_OFF;
        const unsigned sw = (unsigned)(g << 4);
#pragma unroll
        for (int kc = 0; kc < 4; kc++) {
            const unsigned c0 = ((unsigned)(kc * 32) ^ sw) + 4 * t;
            const unsigned c1 = ((unsigned)(kc * 32 + 16) ^ sw) + 4 * t;
            qa[kc][0] = *(const unsigned*)(Qs + (qr + g) * 128 + c0);
            qa[kc][1] = *(const unsigned*)(Qs + (qr + 8 + g) * 128 + c0);
            qa[kc][2] = *(const unsigned*)(Qs + (qr + g) * 128 + c1);
            qa[kc][3] = *(const unsigned*)(Qs + (qr + 8 + g) * 128 + c1);
        }
    }

    float s[8][4];
    auto compute_S = [&](const char* Ks) {
        const unsigned KsU = (unsigned)__cvta_generic_to_shared(Ks);
#pragma unroll
        for (int nt = 0; nt < 8; nt++)
            s[nt][0] = s[nt][1] = s[nt][2] = s[nt][3] = 0.f;
#pragma unroll
        for (int kc = 0; kc < 4; kc++) {
#pragma unroll
            for (int ntp = 0; ntp < 4; ntp++) {
                const int krow = ntp * 16 + ((l8 >> 1) << 3) + l7;
                const int kch = kc * 2 + (l8 & 1);
                unsigned addr = KsU + (unsigned)(krow * 128 +
                                   ((kch * 16) ^ ((krow & 7) << 4)));
                unsigned b0, b1, b2, b3;
                ldsm_x4(b0, b1, b2, b3, addr);
                mma_f16(s[ntp * 2], qa[kc], b0, b1);
                mma_f16(s[ntp * 2 + 1], qa[kc], b2, b3);
            }
        }
    };

    float ml0 = -1e30f, ml1 = -1e30f, l0 = 0.f, l1 = 0.f;  // l = per-thread partial
    float o[8][4];
#pragma unroll
    for (int nt = 0; nt < 8; nt++)
#pragma unroll
        for (int i = 0; i < 4; i++) o[nt][i] = 0.f;

    compute_S(sm);   // S(0)

    for (int kt = 0; kt < NT; kt++) {
        if (kt + 2 < NT) stage_kv(kt + 2, sm + ((kt + 2) % 3) * STG_B);
        CP_COMMIT();

        // ---- softmax on s (=S(kt)) -> P(kt) in Pw; partial-l update ----
        float mx0 = -1e30f, mx1 = -1e30f;
#pragma unroll
        for (int nt = 0; nt < 8; nt++) {
            mx0 = fmaxf(mx0, fmaxf(s[nt][0], s[nt][1]));
            mx1 = fmaxf(mx1, fmaxf(s[nt][2], s[nt][3]));
        }
        mx0 = fmaxf(mx0, __shfl_xor_sync(0xffffffffu, mx0, 1));
        mx0 = fmaxf(mx0, __shfl_xor_sync(0xffffffffu, mx0, 2));
        mx1 = fmaxf(mx1, __shfl_xor_sync(0xffffffffu, mx1, 1));
        mx1 = fmaxf(mx1, __shfl_xor_sync(0xffffffffu, mx1, 2));
        const float mnl0 = fmaxf(ml0, mx0 * L2E), mnl1 = fmaxf(ml1, mx1 * L2E);
        const float a0 = exp2f(ml0 - mnl0), a1 = exp2f(ml1 - mnl1);
        ml0 = mnl0; ml1 = mnl1;

        float sum0 = 0.f, sum1 = 0.f;
#pragma unroll
        for (int nt = 0; nt < 8; nt++) {
            float y0 = fmaf(s[nt][0], L2E, -mnl0);
            float y1 = fmaf(s[nt][1], L2E, -mnl0);
            float y2 = fmaf(s[nt][2], L2E, -mnl1);
            float y3 = fmaf(s[nt][3], L2E, -mnl1);
            unsigned p01 = h2exp2(packh2(y0, y1));
            unsigned p23 = h2exp2(packh2(y2, y3));
            *(unsigned*)(Pw + g * LDP + nt * 16 + 4 * t) = p01;
            *(unsigned*)(Pw + (g + 8) * LDP + nt * 16 + 4 * t) = p23;
            float2 f01 = __half22float2(*(__half2*)&p01);
            float2 f23 = __half22float2(*(__half2*)&p23);
            sum0 += f01.x + f01.y;
            sum1 += f23.x + f23.y;
        }
        l0 = l0 * a0 + sum0;     // per-thread partial; quad-reduced at end
        l1 = l1 * a1 + sum1;

#pragma unroll
        for (int nt = 0; nt < 8; nt++) {
            o[nt][0] *= a0; o[nt][1] *= a0;
            o[nt][2] *= a1; o[nt][3] *= a1;
        }
        __syncwarp();

        const char* Vs = sm + (kt % 3) * STG_B + KVT_B;

        // ---- S(kt+1) preload: fills the STS->ldsm gap of PV(kt) ----
        if (kt + 1 < NT) compute_S(sm + ((kt + 1) % 3) * STG_B);

        // ---- O += P(kt) @ V(kt) ----
        const unsigned VsU = (unsigned)__cvta_generic_to_shared(Vs);
        const int midx = lane >> 3, mr = lane & 7;
#pragma unroll
        for (int kc = 0; kc < 4; kc++) {
            unsigned pa[4];
            ldsm_x4(pa[0], pa[1], pa[2], pa[3],
                    PwU + (unsigned)((((l8 & 1) << 3) + l7) * LDP +
                                     kc * 32 + ((l8 >> 1) << 4)));
#pragma unroll
            for (int ntp = 0; ntp < 4; ntp++) {
                const int nt = ntp * 2 + (midx >> 1);
                const int key = kc * 16 + (midx & 1) * 8 + mr;
                unsigned addr = VsU + (unsigned)(key * 128 + ((nt * 16) ^ ((key & 7) << 4)));
                unsigned r0, r1, r2, r3;
                ldsm_x4_trans(r0, r1, r2, r3, addr);
                mma_f16(o[ntp * 2], pa, r0, r1);
                mma_f16(o[ntp * 2 + 1], pa, r2, r3);
            }
        }

        CP_WAIT0();
        __syncthreads();   // stage kt+2 landed; all warps done with V(kt)
    }

    // ---- final l reduction + epilogue ----
    l0 += __shfl_xor_sync(0xffffffffu, l0, 1);
    l0 += __shfl_xor_sync(0xffffffffu, l0, 2);
    l1 += __shfl_xor_sync(0xffffffffu, l1, 1);
    l1 += __shfl_xor_sync(0xffffffffu, l1, 2);
    const float i0 = 1.f / l0, i1 = 1.f / l1;
    __half* Ob = O + ((size_t)(b * SEQ + qt * 128 + qr)) * INNER + h * DHEAD;
#pragma unroll
    for (int nt = 0; nt < 8; nt++) {
        *(unsigned*)&Ob[(size_t)g * INNER + nt * 8 + 2 * t] =
            packh2(o[nt][0] * i0, o[nt][1] * i0);
        *(unsigned*)&Ob[(size_t)(g + 8) * INNER + nt * 8 + 2 * t] =
            packh2(o[nt][2] * i1, o[nt][3] * i1);
    }
}

// ---------------------------------------------------------------------------
extern "C" void kernel_launch(void* const* d_in, const int* in_sizes, int n_in,
                              void* d_out, int out_size) {
    const float* x  = (const float*)d_in[0];
    const float* Wq = (const float*)d_in[1];
    const float* Wk = (const float*)d_in[2];
    const float* Wv = (const float*)d_in[3];
    const float* Wo = (const float*)d_in[4];
    const float* bo = (const float*)d_in[5];
    float* out = (float*)d_out;

    __half *q, *k, *v, *a, *rx, *rwq, *rwk, *rwv, *rwo;
    cudaGetSymbolAddress((void**)&q, g_q);
    cudaGetSymbolAddress((void**)&k, g_k);
    cudaGetSymbolAddress((void**)&v, g_v);
    cudaGetSymbolAddress((void**)&a, g_a);
    cudaGetSymbolAddress((void**)&rx, g_rx);
    cudaGetSymbolAddress((void**)&rwq, g_rwq);
    cudaGetSymbolAddress((void**)&rwk, g_rwk);
    cudaGetSymbolAddress((void**)&rwv, g_rwv);
    cudaGetSymbolAddress((void**)&rwo, g_rwo);

    cudaFuncSetAttribute((const void*)gemm_f16<false>,
                         cudaFuncAttributeMaxDynamicSharedMemorySize, GEMM_SMEM);
    cudaFuncSetAttribute((const void*)gemm_f16<true>,
                         cudaFuncAttributeMaxDynamicSharedMemorySize, GEMM_SMEM);
    cudaFuncSetAttribute((const void*)attn_fa2,
                         cudaFuncAttributeMaxDynamicSharedMemorySize, ATTN_SMEM);

    to_half_k<<<(MROWS * DIM / 4 + 255) / 256, 256>>>(rx, x, MROWS * DIM / 4);
    transpose_half4<<<dim3(32, 32, 4), dim3(32, 8)>>>(rwq, rwk, rwv, rwo,
                                                      Wq, Wk, Wv, Wo);

    gemm_f16<false><<<dim3(INNER / 128, MROWS / 128, 3), 256, GEMM_SMEM>>>(
        rx, rwq, rwk, rwv, q, k, v, nullptr);

    attn_fa2<<<dim3(SEQ / 128, NHEAD, BATCH), 256, ATTN_SMEM>>>(q, k, v, a);

    gemm_f16<true><<<dim3(DIM / 128, MROWS / 128, 1), 256, GEMM_SMEM>>>(
        a, rwo, rwo, rwo, out, out, out, bo);
}

// round 11
// speedup vs baseline: 7.2892x; 1.0288x over previous
#include <cuda_runtime.h>
#include <cuda_fp16.h>
#include <cstdint>
#include <cstddef>

#define DIM    1024
#define INNER  1024
#define NHEAD  16
#define DHEAD  64
#define BATCH  2
#define SEQ    2048
#define MROWS  (BATCH * SEQ)
#define ATTN_SCALE 0.125f
#define L2E 1.4426950408889634f

// Scratch (__device__ globals; allocation-free rule)
__device__ __half g_q[MROWS * INNER];
__device__ __half g_k[MROWS * INNER];
__device__ __half g_v[MROWS * INNER];
__device__ __half g_a[MROWS * INNER];
__device__ __half g_rx[MROWS * DIM];
__device__ __half g_rwq[DIM * INNER];   // K-major (transposed) fp16 weights
__device__ __half g_rwk[DIM * INNER];
__device__ __half g_rwv[DIM * INNER];
__device__ __half g_rwo[INNER * DIM];

__device__ __forceinline__ void cpa16(void* dst, const void* src) {
    unsigned d = (unsigned)__cvta_generic_to_shared(dst);
    asm volatile("cp.async.cg.shared.global [%0], [%1], 16;\n" :: "r"(d), "l"(src));
}
#define CP_COMMIT() asm volatile("cp.async.commit_group;\n" ::: "memory")
#define CP_WAIT0()  asm volatile("cp.async.wait_group 0;\n" ::: "memory")
#define CP_WAIT1()  asm volatile("cp.async.wait_group 1;\n" ::: "memory")

__device__ __forceinline__ void mma_f16(float c[4], const unsigned a[4],
                                        unsigned b0, unsigned b1) {
    asm volatile(
        "mma.sync.aligned.m16n8k16.row.col.f32.f16.f16.f32 "
        "{%0,%1,%2,%3}, {%4,%5,%6,%7}, {%8,%9}, {%0,%1,%2,%3};\n"
        : "+f"(c[0]), "+f"(c[1]), "+f"(c[2]), "+f"(c[3])
        : "r"(a[0]), "r"(a[1]), "r"(a[2]), "r"(a[3]), "r"(b0), "r"(b1));
}
__device__ __forceinline__ void ldsm_x4(unsigned& r0, unsigned& r1,
                                        unsigned& r2, unsigned& r3, unsigned addr) {
    asm volatile("ldmatrix.sync.aligned.m8n8.x4.shared.b16 {%0,%1,%2,%3}, [%4];"
                 : "=r"(r0), "=r"(r1), "=r"(r2), "=r"(r3) : "r"(addr));
}
__device__ __forceinline__ void ldsm_x4_trans(unsigned& r0, unsigned& r1,
                                              unsigned& r2, unsigned& r3,
                                              unsigned addr) {
    asm volatile("ldmatrix.sync.aligned.m8n8.x4.trans.shared.b16 {%0,%1,%2,%3}, [%4];"
                 : "=r"(r0), "=r"(r1), "=r"(r2), "=r"(r3) : "r"(addr));
}
__device__ __forceinline__ unsigned packh2(float a, float b) {
    __half2 h = __floats2half2_rn(a, b);
    return *(unsigned*)&h;
}
__device__ __forceinline__ unsigned h2exp2(unsigned y) {
    unsigned p;
    asm("ex2.approx.f16x2 %0, %1;" : "=r"(p) : "r"(y));
    return p;
}

// ---------------------------------------------------------------------------
// prep
// ---------------------------------------------------------------------------
__global__ void to_half_k(__half* __restrict__ d, const float* __restrict__ s, int n4) {
    int i = blockIdx.x * blockDim.x + threadIdx.x;
    if (i < n4) {
        float4 v = ((const float4*)s)[i];
        ((__half2*)d)[2 * i]     = __floats2half2_rn(v.x, v.y);
        ((__half2*)d)[2 * i + 1] = __floats2half2_rn(v.z, v.w);
    }
}
__global__ void transpose_half4(__half* w0, __half* w1, __half* w2, __half* w3,
                                const float* s0, const float* s1,
                                const float* s2, const float* s3) {
    __shared__ float tile[32][33];
    const int z = blockIdx.z;
    const float* src = z == 0 ? s0 : (z == 1 ? s1 : (z == 2 ? s2 : s3));
    __half* dst = z == 0 ? w0 : (z == 1 ? w1 : (z == 2 ? w2 : w3));
    const int bx = blockIdx.x * 32, by = blockIdx.y * 32;
    const int tx = threadIdx.x, ty = threadIdx.y;
#pragma unroll
    for (int i = 0; i < 32; i += 8)
        tile[ty + i][tx] = src[(size_t)(by + ty + i) * 1024 + bx + tx];
    __syncthreads();
#pragma unroll
    for (int i = 0; i < 32; i += 8)
        dst[(size_t)(bx + ty + i) * 1024 + by + tx] = __float2half(tile[tx][ty + i]);
}

// ---------------------------------------------------------------------------
// fp16 GEMM (unchanged): 128x128, BK=32, 3-stage cp.async, ldmatrix.
// ---------------------------------------------------------------------------
#define GLD 80
#define GOPB (128 * GLD)
#define GSTGB (2 * GOPB)
#define GEMM_SMEM (3 * GSTGB)

template <bool OUT_FP32>
__global__ __launch_bounds__(256, 2)
void gemm_f16(const __half* __restrict__ A,
              const __half* __restrict__ B0, const __half* __restrict__ B1,
              const __half* __restrict__ B2,
              void* C0, void* C1, void* C2, const float* __restrict__ bo) {
    extern __shared__ char smg[];
    const int tid = threadIdx.x;
    const int warp = tid >> 5;
    const int lane = tid & 31;
    const int g = lane >> 2, t = lane & 3;
    const int l8 = lane >> 3, l7 = lane & 7;
    const int wm = warp >> 1, wn = warp & 1;
    const int bx = blockIdx.x, by = blockIdx.y, bz = blockIdx.z;

    const __half* Bt = bz == 0 ? B0 : (bz == 1 ? B1 : B2);
    void* Cp = bz == 0 ? C0 : (bz == 1 ? C1 : C2);

    const __half* Ag = A + (size_t)(by * 128) * DIM;
    const __half* Bg = Bt + (size_t)(bx * 128) * DIM;

    float acc[2][8][4];
#pragma unroll
    for (int mt = 0; mt < 2; mt++)
#pragma unroll
        for (int nt = 0; nt < 8; nt++)
#pragma unroll
            for (int i = 0; i < 4; i++) acc[mt][nt][i] = 0.f;

    const int sr = tid >> 1;
    const int sc = (tid & 1) * 2;

    auto stage = [&](int k0, char* s) {
        char* sA = s;
        char* sB = s + GOPB;
#pragma unroll
        for (int c = 0; c < 2; c++) {
            int ch = sc + c;
            cpa16(sA + sr * GLD + ch * 16, Ag + (size_t)sr * DIM + k0 + ch * 8);
            cpa16(sB + sr * GLD + ch * 16, Bg + (size_t)sr * DIM + k0 + ch * 8);
        }
    };

    stage(0, smg);              CP_COMMIT();
    stage(32, smg + GSTGB);     CP_COMMIT();

    const int a_r = ((l8 & 1) << 3) + l7;
    const int a_c = (l8 >> 1) << 4;
    const int b_r = ((l8 >> 1) << 3) + l7;
    const int b_c = (l8 & 1) << 4;

    for (int it = 0; it < 32; it++) {
        CP_WAIT1();
        __syncthreads();
        if (it + 2 < 32) stage((it + 2) * 32, smg + ((it + 2) % 3) * GSTGB);
        CP_COMMIT();
        const unsigned sAu = (unsigned)__cvta_generic_to_shared(smg + (it % 3) * GSTGB);
        const unsigned sBu = sAu + GOPB;
#pragma unroll
        for (int kc = 0; kc < 2; kc++) {
            unsigned a[2][4];
#pragma unroll
            for (int mt = 0; mt < 2; mt++)
                ldsm_x4(a[mt][0], a[mt][1], a[mt][2], a[mt][3],
                        sAu + (wm * 32 + mt * 16 + a_r) * GLD + kc * 32 + a_c);
#pragma unroll
            for (int ntp = 0; ntp < 4; ntp++) {
                unsigned b0, b1, b2, b3;
                ldsm_x4(b0, b1, b2, b3,
                        sBu + (wn * 64 + ntp * 16 + b_r) * GLD + kc * 32 + b_c);
                mma_f16(acc[0][ntp * 2], a[0], b0, b1);
                mma_f16(acc[1][ntp * 2], a[1], b0, b1);
                mma_f16(acc[0][ntp * 2 + 1], a[0], b2, b3);
                mma_f16(acc[1][ntp * 2 + 1], a[1], b2, b3);
            }
        }
    }

    const float qsc = (!OUT_FP32 && bz == 0) ? ATTN_SCALE : 1.f;
#pragma unroll
    for (int mt = 0; mt < 2; mt++) {
#pragma unroll
        for (int nt = 0; nt < 8; nt++) {
            const int row = by * 128 + wm * 32 + mt * 16;
            const int col = bx * 128 + wn * 64 + nt * 8 + 2 * t;
            if (OUT_FP32) {
                float* C = (float*)Cp;
                float2 v0, v1;
                v0.x = acc[mt][nt][0] + bo[col];
                v0.y = acc[mt][nt][1] + bo[col + 1];
                v1.x = acc[mt][nt][2] + bo[col];
                v1.y = acc[mt][nt][3] + bo[col + 1];
                *(float2*)&C[(size_t)(row + g) * 1024 + col] = v0;
                *(float2*)&C[(size_t)(row + 8 + g) * 1024 + col] = v1;
            } else {
                __half* C = (__half*)Cp;
                *(unsigned*)&C[(size_t)(row + g) * 1024 + col] =
                    packh2(acc[mt][nt][0] * qsc, acc[mt][nt][1] * qsc);
                *(unsigned*)&C[(size_t)(row + 8 + g) * 1024 + col] =
                    packh2(acc[mt][nt][2] * qsc, acc[mt][nt][3] * qsc);
            }
        }
    }
}

// ---------------------------------------------------------------------------
// FlashAttention-2 fp16: P kept in registers (C-frag == A-frag identity),
// S(kt+1) preload between softmax and PV, deferred l reduction.
// ---------------------------------------------------------------------------
#define KT 64
#define KVT_B (64 * 128)
#define STG_B (2 * KVT_B)
#define QS_OFF (3 * STG_B)
#define ATTN_SMEM (QS_OFF + 128 * 128)
#define NT (SEQ / KT)

__global__ __launch_bounds__(256, 2)
void attn_fa2(const __half* __restrict__ Q, const __half* __restrict__ K,
              const __half* __restrict__ V, __half* __restrict__ O) {
    extern __shared__ char sm[];
    const int tid  = threadIdx.x;
    const int warp = tid >> 5;
    const int lane = tid & 31;
    const int g = lane >> 2, t = lane & 3;
    const int l8 = lane >> 3, l7 = lane & 7;
    const int qt = blockIdx.x, h = blockIdx.y, b = blockIdx.z;

    const __half* Qb = Q + ((size_t)(b * SEQ + qt * 128)) * INNER + h * DHEAD;
    const __half* Kb = K + (size_t)b * SEQ * INNER + h * DHEAD;
    const __half* Vb = V + (size_t)b * SEQ * INNER + h * DHEAD;

    auto stage_kv = [&](int kt, char* buf) {
        const int r = tid >> 2;
        const int j0 = (tid & 3) * 2;
        const size_t go = (size_t)(kt * KT + r) * INNER;
#pragma unroll
        for (int c = 0; c < 2; c++) {
            int j = j0 + c;
            unsigned off = (unsigned)(r * 128 + ((j * 16) ^ ((r & 7) << 4)));
            cpa16(buf + off, Kb + go + j * 8);
            cpa16(buf + KVT_B + off, Vb + go + j * 8);
        }
    };

    // prologue: Q + KV0 (group 0), KV1 (group 1)
    {
        const int r = tid >> 1;
        const int j0 = (tid & 1) * 4;
#pragma unroll
        for (int c = 0; c < 4; c++) {
            int j = j0 + c;
            unsigned off = (unsigned)(r * 128 + ((j * 16) ^ ((r & 7) << 4)));
            cpa16(sm + QS_OFF + off, Qb + (size_t)r * INNER + j * 8);
        }
    }
    stage_kv(0, sm);            CP_COMMIT();
    stage_kv(1, sm + STG_B);    CP_COMMIT();

    const int qr = warp * 16;
    CP_WAIT0();
    __syncthreads();

    // Q fragments
    unsigned qa[4][4];
    {
        const char* Qs = sm + QS_OFF;
        const unsigned sw = (unsigned)(g << 4);
#pragma unroll
        for (int kc = 0; kc < 4; kc++) {
            const unsigned c0 = ((unsigned)(kc * 32) ^ sw) + 4 * t;
            const unsigned c1 = ((unsigned)(kc * 32 + 16) ^ sw) + 4 * t;
            qa[kc][0] = *(const unsigned*)(Qs + (qr + g) * 128 + c0);
            qa[kc][1] = *(const unsigned*)(Qs + (qr + 8 + g) * 128 + c0);
            qa[kc][2] = *(const unsigned*)(Qs + (qr + g) * 128 + c1);
            qa[kc][3] = *(const unsigned*)(Qs + (qr + 8 + g) * 128 + c1);
        }
    }

    float s[8][4];
    auto compute_S = [&](const char* Ks) {
        const unsigned KsU = (unsigned)__cvta_generic_to_shared(Ks);
#pragma unroll
        for (int nt = 0; nt < 8; nt++)
            s[nt][0] = s[nt][1] = s[nt][2] = s[nt][3] = 0.f;
#pragma unroll
        for (int kc = 0; kc < 4; kc++) {
#pragma unroll
            for (int ntp = 0; ntp < 4; ntp++) {
                const int krow = ntp * 16 + ((l8 >> 1) << 3) + l7;
                const int kch = kc * 2 + (l8 & 1);
                unsigned addr = KsU + (unsigned)(krow * 128 +
                                   ((kch * 16) ^ ((krow & 7) << 4)));
                unsigned b0, b1, b2, b3;
                ldsm_x4(b0, b1, b2, b3, addr);
                mma_f16(s[ntp * 2], qa[kc], b0, b1);
                mma_f16(s[ntp * 2 + 1], qa[kc], b2, b3);
            }
        }
    };

    float ml0 = -1e30f, ml1 = -1e30f, l0 = 0.f, l1 = 0.f;
    float o[8][4];
#pragma unroll
    for (int nt = 0; nt < 8; nt++)
#pragma unroll
        for (int i = 0; i < 4; i++) o[nt][i] = 0.f;

    compute_S(sm);   // S(0)

    for (int kt = 0; kt < NT; kt++) {
        if (kt + 2 < NT) stage_kv(kt + 2, sm + ((kt + 2) % 3) * STG_B);
        CP_COMMIT();

        // ---- softmax: s -> pregs (P in A-fragment register layout) ----
        float mx0 = -1e30f, mx1 = -1e30f;
#pragma unroll
        for (int nt = 0; nt < 8; nt++) {
            mx0 = fmaxf(mx0, fmaxf(s[nt][0], s[nt][1]));
            mx1 = fmaxf(mx1, fmaxf(s[nt][2], s[nt][3]));
        }
        mx0 = fmaxf(mx0, __shfl_xor_sync(0xffffffffu, mx0, 1));
        mx0 = fmaxf(mx0, __shfl_xor_sync(0xffffffffu, mx0, 2));
        mx1 = fmaxf(mx1, __shfl_xor_sync(0xffffffffu, mx1, 1));
        mx1 = fmaxf(mx1, __shfl_xor_sync(0xffffffffu, mx1, 2));
        const float mnl0 = fmaxf(ml0, mx0 * L2E), mnl1 = fmaxf(ml1, mx1 * L2E);
        const float a0 = exp2f(ml0 - mnl0), a1 = exp2f(ml1 - mnl1);
        ml0 = mnl0; ml1 = mnl1;

        unsigned pregs[8][2];       // [nt][0]: rows g (cols 2t,2t+1); [1]: rows g+8
        float sum0 = 0.f, sum1 = 0.f;
#pragma unroll
        for (int nt = 0; nt < 8; nt++) {
            float y0 = fmaf(s[nt][0], L2E, -mnl0);
            float y1 = fmaf(s[nt][1], L2E, -mnl0);
            float y2 = fmaf(s[nt][2], L2E, -mnl1);
            float y3 = fmaf(s[nt][3], L2E, -mnl1);
            pregs[nt][0] = h2exp2(packh2(y0, y1));
            pregs[nt][1] = h2exp2(packh2(y2, y3));
            float2 f01 = __half22float2(*(__half2*)&pregs[nt][0]);
            float2 f23 = __half22float2(*(__half2*)&pregs[nt][1]);
            sum0 += f01.x + f01.y;
            sum1 += f23.x + f23.y;
        }
        l0 = l0 * a0 + sum0;
        l1 = l1 * a1 + sum1;

#pragma unroll
        for (int nt = 0; nt < 8; nt++) {
            o[nt][0] *= a0; o[nt][1] *= a0;
            o[nt][2] *= a1; o[nt][3] *= a1;
        }

        const char* Vs = sm + (kt % 3) * STG_B + KVT_B;

        // ---- S(kt+1) preload (s regs free; P lives in pregs) ----
        if (kt + 1 < NT) compute_S(sm + ((kt + 1) % 3) * STG_B);

        // ---- O += P @ V : P direct from registers, V via ldmatrix.trans ----
        const unsigned VsU = (unsigned)__cvta_generic_to_shared(Vs);
        const int midx = lane >> 3, mr = lane & 7;
#pragma unroll
        for (int kc = 0; kc < 4; kc++) {
            unsigned pa[4];
            pa[0] = pregs[2 * kc][0];
            pa[1] = pregs[2 * kc][1];
            pa[2] = pregs[2 * kc + 1][0];
            pa[3] = pregs[2 * kc + 1][1];
#pragma unroll
            for (int ntp = 0; ntp < 4; ntp++) {
                const int nt = ntp * 2 + (midx >> 1);
                const int key = kc * 16 + (midx & 1) * 8 + mr;
                unsigned addr = VsU + (unsigned)(key * 128 + ((nt * 16) ^ ((key & 7) << 4)));
                unsigned r0, r1, r2, r3;
                ldsm_x4_trans(r0, r1, r2, r3, addr);
                mma_f16(o[ntp * 2], pa, r0, r1);
                mma_f16(o[ntp * 2 + 1], pa, r2, r3);
            }
        }

        CP_WAIT0();
        __syncthreads();   // stage kt+2 landed; all warps done with V(kt)
    }

    // ---- final l reduction + epilogue ----
    l0 += __shfl_xor_sync(0xffffffffu, l0, 1);
    l0 += __shfl_xor_sync(0xffffffffu, l0, 2);
    l1 += __shfl_xor_sync(0xffffffffu, l1, 1);
    l1 += __shfl_xor_sync(0xffffffffu, l1, 2);
    const float i0 = 1.f / l0, i1 = 1.f / l1;
    __half* Ob = O + ((size_t)(b * SEQ + qt * 128 + qr)) * INNER + h * DHEAD;
#pragma unroll
    for (int nt = 0; nt < 8; nt++) {
        *(unsigned*)&Ob[(size_t)g * INNER + nt * 8 + 2 * t] =
            packh2(o[nt][0] * i0, o[nt][1] * i0);
        *(unsigned*)&Ob[(size_t)(g + 8) * INNER + nt * 8 + 2 * t] =
            packh2(o[nt][2] * i1, o[nt][3] * i1);
    }
}

// ---------------------------------------------------------------------------
extern "C" void kernel_launch(void* const* d_in, const int* in_sizes, int n_in,
                              void* d_out, int out_size) {
    const float* x  = (const float*)d_in[0];
    const float* Wq = (const float*)d_in[1];
    const float* Wk = (const float*)d_in[2];
    const float* Wv = (const float*)d_in[3];
    const float* Wo = (const float*)d_in[4];
    const float* bo = (const float*)d_in[5];
    float* out = (float*)d_out;

    __half *q, *k, *v, *a, *rx, *rwq, *rwk, *rwv, *rwo;
    cudaGetSymbolAddress((void**)&q, g_q);
    cudaGetSymbolAddress((void**)&k, g_k);
    cudaGetSymbolAddress((void**)&v, g_v);
    cudaGetSymbolAddress((void**)&a, g_a);
    cudaGetSymbolAddress((void**)&rx, g_rx);
    cudaGetSymbolAddress((void**)&rwq, g_rwq);
    cudaGetSymbolAddress((void**)&rwk, g_rwk);
    cudaGetSymbolAddress((void**)&rwv, g_rwv);
    cudaGetSymbolAddress((void**)&rwo, g_rwo);

    cudaFuncSetAttribute((const void*)gemm_f16<false>,
                         cudaFuncAttributeMaxDynamicSharedMemorySize, GEMM_SMEM);
    cudaFuncSetAttribute((const void*)gemm_f16<true>,
                         cudaFuncAttributeMaxDynamicSharedMemorySize, GEMM_SMEM);
    cudaFuncSetAttribute((const void*)attn_fa2,
                         cudaFuncAttributeMaxDynamicSharedMemorySize, ATTN_SMEM);

    to_half_k<<<(MROWS * DIM / 4 + 255) / 256, 256>>>(rx, x, MROWS * DIM / 4);
    transpose_half4<<<dim3(32, 32, 4), dim3(32, 8)>>>(rwq, rwk, rwv, rwo,
                                                      Wq, Wk, Wv, Wo);

    gemm_f16<false><<<dim3(INNER / 128, MROWS / 128, 3), 256, GEMM_SMEM>>>(
        rx, rwq, rwk, rwv, q, k, v, nullptr);

    attn_fa2<<<dim3(SEQ / 128, NHEAD, BATCH), 256, ATTN_SMEM>>>(q, k, v, a);

    gemm_f16<true><<<dim3(DIM / 128, MROWS / 128, 1), 256, GEMM_SMEM>>>(
        a, rwo, rwo, rwo, out, out, out, bo);
}